// round 4
// baseline (speedup 1.0000x reference)
#include <cuda_runtime.h>
#include <cuda_bf16.h>
#include <cstdint>
#include <cstddef>

// ---------------------------------------------------------------------------
// Cayley-Dickson sign table:  e_i * e_j = sign(i,j) * e_{i XOR j}
// ---------------------------------------------------------------------------
constexpr int cdsign(int i, int j, int n) {
    return (n == 1) ? 1
         : (i < n/2 && j < n/2) ? cdsign(i, j, n/2)
         : (i < n/2)            ? cdsign(j - n/2, i, n/2)
         : (j < n/2)            ? cdsign(i - n/2, j, n/2) * (j == 0 ? 1 : -1)
         : -cdsign(j - n/2, i - n/2, n/2) * ((j - n/2) == 0 ? 1 : -1);
}
struct SgnTab { signed char v[16][16]; };
constexpr SgnTab make_sgn() {
    SgnTab t{};
    for (int i = 0; i < 16; ++i)
        for (int j = 0; j < 16; ++j)
            t.v[i][j] = (signed char)cdsign(i, j, 16);
    return t;
}
__constant__ SgnTab c_SGN = make_sgn();

// ---------------------------------------------------------------------------
static constexpr int C = 128, NPIX = 8 * 128 * 128;   // 131072
static constexpr int CH = 512;

// fp32 buffers
__device__ float g_xt[NPIX * C];
__device__ float g_y [NPIX * C];

// bf16 split operand buffers
__device__ __align__(256) __nv_bfloat16 g_xnh[NPIX * C];
__device__ __align__(256) __nv_bfloat16 g_xnl[NPIX * C];
__device__ __align__(256) __nv_bfloat16 g_gh [NPIX * C];
__device__ __align__(256) __nv_bfloat16 g_gl [NPIX * C];
__device__ __align__(256) __nv_bfloat16 g_ynh[NPIX * C];
__device__ __align__(256) __nv_bfloat16 g_ynl[NPIX * C];
__device__ __align__(256) __nv_bfloat16 g_hh [NPIX * CH];
__device__ __align__(256) __nv_bfloat16 g_hl [NPIX * CH];
// weight (B^T, n-major rows of K) buffers
__device__ __align__(256) __nv_bfloat16 g_bth[2048 * 2048];
__device__ __align__(256) __nv_bfloat16 g_btl[2048 * 2048];
__device__ __align__(256) __nv_bfloat16 g_bph[128 * 128];
__device__ __align__(256) __nv_bfloat16 g_bpl[128 * 128];
__device__ __align__(256) __nv_bfloat16 g_b1h[512 * 128];
__device__ __align__(256) __nv_bfloat16 g_b1l[512 * 128];
__device__ __align__(256) __nv_bfloat16 g_b2h[128 * 512];
__device__ __align__(256) __nv_bfloat16 g_b2l[128 * 512];

// ---------------------------------------------------------------------------
// PTX helpers (sm_80-compatible: cp.async, ldmatrix, mma.sync)
// ---------------------------------------------------------------------------
__device__ __forceinline__ uint32_t smem_u32(const void* p) {
    uint32_t a;
    asm("{ .reg .u64 t; cvta.to.shared.u64 t, %1; cvt.u32.u64 %0, t; }"
        : "=r"(a) : "l"(p));
    return a;
}
__device__ __forceinline__ void cp16(uint32_t dst, const void* src) {
    asm volatile("cp.async.cg.shared.global [%0], [%1], 16;" :: "r"(dst), "l"(src));
}
#define CP_COMMIT() asm volatile("cp.async.commit_group;" ::: "memory")
template<int N>
__device__ __forceinline__ void cp_wait() {
    asm volatile("cp.async.wait_group %0;" :: "n"(N) : "memory");
}
__device__ __forceinline__ void ldsm_x4(uint32_t addr, uint32_t* r) {
    asm volatile("ldmatrix.sync.aligned.m8n8.x4.shared.b16 {%0,%1,%2,%3}, [%4];"
        : "=r"(r[0]), "=r"(r[1]), "=r"(r[2]), "=r"(r[3]) : "r"(addr));
}
__device__ __forceinline__ void mma16816(float* c, const uint32_t* a, const uint32_t* b) {
    asm volatile("mma.sync.aligned.m16n8k16.row.col.f32.bf16.bf16.f32 "
        "{%0,%1,%2,%3}, {%4,%5,%6,%7}, {%8,%9}, {%0,%1,%2,%3};"
        : "+f"(c[0]), "+f"(c[1]), "+f"(c[2]), "+f"(c[3])
        : "r"(a[0]), "r"(a[1]), "r"(a[2]), "r"(a[3]), "r"(b[0]), "r"(b[1]));
}
__device__ __forceinline__ uint32_t swz(uint32_t off) {
    return off ^ ((off >> 3) & 0x70);
}
__device__ __forceinline__ float gelu_exact(float v) {
    return 0.5f * v * (1.0f + erff(v * 0.7071067811865476f));
}
__device__ __forceinline__ void split_bf16(float v, __nv_bfloat16& h, __nv_bfloat16& l) {
    h = __float2bfloat16_rn(v);
    l = __float2bfloat16_rn(v - __bfloat162float(h));
}

// ---------------------------------------------------------------------------
// LN1 + NCHW -> window-major (writes xt fp32 and xn hi/lo bf16)
// ---------------------------------------------------------------------------
__global__ void k_ln1(const float* __restrict__ x,
                      const float* __restrict__ g1,
                      const float* __restrict__ b1,
                      float* __restrict__ xt,
                      __nv_bfloat16* __restrict__ xnh,
                      __nv_bfloat16* __restrict__ xnl) {
    __shared__ float sh[128][33];
    __shared__ float red[2][8][32];
    __shared__ float smean[32], srstd[32];

    const int b  = blockIdx.y;
    const int s0 = blockIdx.x * 32;
    const int tp = threadIdx.x & 31;
    const int ty = threadIdx.x >> 5;

    const float* xb = x + (size_t)b * 128 * 16384 + s0;
    float sum = 0.f, sq = 0.f;
    #pragma unroll
    for (int c0 = 0; c0 < 128; c0 += 8) {
        int c = c0 + ty;
        float v = xb[(size_t)c * 16384 + tp];
        sh[c][tp] = v;
        sum += v; sq += v * v;
    }
    red[0][ty][tp] = sum; red[1][ty][tp] = sq;
    __syncthreads();
    if (ty == 0) {
        float s = 0.f, q = 0.f;
        #pragma unroll
        for (int y = 0; y < 8; ++y) { s += red[0][y][tp]; q += red[1][y][tp]; }
        float m = s * (1.0f / 128.0f);
        smean[tp] = m;
        srstd[tp] = rsqrtf(q * (1.0f / 128.0f) - m * m + 1e-5f);
    }
    __syncthreads();

    for (int l = threadIdx.x; l < 32 * 128; l += 256) {
        int p = l >> 7, c = l & 127;
        int s = s0 + p;
        int hh = s >> 7, ww = s & 127;
        int row = ((((b * 32 + (hh >> 2)) * 32 + (ww >> 2)) << 4)
                  + ((hh & 3) << 2) + (ww & 3));
        float v = sh[c][p];
        size_t idx = (size_t)row * 128 + c;
        xt[idx] = v;
        float nv = (v - smean[p]) * srstd[p] * g1[c] + b1[c];
        __nv_bfloat16 h, lo; split_bf16(nv, h, lo);
        xnh[idx] = h; xnl[idx] = lo;
    }
}

// ---------------------------------------------------------------------------
// Weight preps
// ---------------------------------------------------------------------------
__global__ void k_prep_sed(const float* __restrict__ sed_w,
                           __nv_bfloat16* __restrict__ bh,
                           __nv_bfloat16* __restrict__ bl) {
    int n = blockIdx.x;
    int nblk = n >> 7, d = n & 127;
    for (int k = threadIdx.x; k < 2048; k += 128) {
        int i = k >> 7, c = k & 127;
        int j = i ^ nblk;
        float s = (float)c_SGN.v[i][j];
        float v = s * __ldg(&sed_w[(size_t)(j * 128 + c) * 128 + d]);
        __nv_bfloat16 h, lo; split_bf16(v, h, lo);
        size_t idx = (size_t)n * 2048 + k;
        bh[idx] = h; bl[idx] = lo;
    }
}

__global__ void k_prep_w(const float* __restrict__ W, int K, int N,
                         __nv_bfloat16* __restrict__ bh,
                         __nv_bfloat16* __restrict__ bl) {
    int n = blockIdx.x;
    for (int k = threadIdx.x; k < K; k += 128) {
        float v = __ldg(&W[(size_t)k * N + n]);
        __nv_bfloat16 h, lo; split_bf16(v, h, lo);
        size_t idx = (size_t)n * K + k;
        bh[idx] = h; bl[idx] = lo;
    }
}

// ---------------------------------------------------------------------------
// SED GEMM: 256x128 CTA tile, 512 threads / 16 warps (8m x 2n), warp 32x64.
// D = Ah*Bh + Ah*Bl + Al*Bh (fp32 accum).  KITERS = 32 (K = 2048).
// Epilogue: gelu -> bf16 hi/lo.
// ---------------------------------------------------------------------------
static constexpr int SED_STAGE = 98304;            // Ah32K Al32K Bh16K Bl16K
static constexpr int SED_SMEM  = 2 * SED_STAGE;    // 192 KB

__global__ void __launch_bounds__(512, 1)
k_sed(const __nv_bfloat16* __restrict__ Ah, const __nv_bfloat16* __restrict__ Al,
      const __nv_bfloat16* __restrict__ Bh, const __nv_bfloat16* __restrict__ Bl,
      __nv_bfloat16* __restrict__ outh, __nv_bfloat16* __restrict__ outl) {
    extern __shared__ __align__(1024) char smem[];
    const uint32_t sb  = smem_u32(smem);
    const int tid  = threadIdx.x;
    const int wid  = tid >> 5;
    const int lane = tid & 31;
    const int wm   = wid & 7;        // 8 M blocks of 32
    const int wn   = wid >> 3;       // 2 N blocks of 64
    const int mrow0 = blockIdx.y * 256;
    const int n0    = blockIdx.x * 128;
    const size_t pitch = 4096;       // 2048 K * 2B

    const char* sAh = (const char*)Ah + (size_t)mrow0 * pitch;
    const char* sAl = (const char*)Al + (size_t)mrow0 * pitch;
    const char* sBh = (const char*)Bh + (size_t)n0 * pitch;
    const char* sBl = (const char*)Bl + (size_t)n0 * pitch;

    float acc[2][8][4];
    #pragma unroll
    for (int mt = 0; mt < 2; ++mt)
        #pragma unroll
        for (int nt = 0; nt < 8; ++nt)
            #pragma unroll
            for (int q = 0; q < 4; ++q) acc[mt][nt][q] = 0.f;

    auto load_stage = [&](int stage, int kt) {
        uint32_t st = sb + (uint32_t)stage * SED_STAGE;
        const char* bh_ = sBh + (size_t)kt * 128;
        const char* bl_ = sBl + (size_t)kt * 128;
        const char* ah_ = sAh + (size_t)kt * 128;
        const char* al_ = sAl + (size_t)kt * 128;
        #pragma unroll
        for (int i = 0; i < 4; ++i) {                  // Ah: 2048 chunks
            int l = tid + (i << 9);
            int r = l >> 3, ch = l & 7;
            uint32_t off = (uint32_t)(r * 128 + ch * 16);
            cp16(st + swz(off), ah_ + (size_t)r * pitch + ch * 16);
        }
        #pragma unroll
        for (int i = 0; i < 4; ++i) {                  // Al
            int l = tid + (i << 9);
            int r = l >> 3, ch = l & 7;
            uint32_t off = (uint32_t)(r * 128 + ch * 16);
            cp16(st + 32768 + swz(off), al_ + (size_t)r * pitch + ch * 16);
        }
        #pragma unroll
        for (int i = 0; i < 2; ++i) {                  // Bh: 1024 chunks
            int l = tid + (i << 9);
            int r = l >> 3, ch = l & 7;
            uint32_t off = (uint32_t)(r * 128 + ch * 16);
            cp16(st + 65536 + swz(off), bh_ + (size_t)r * pitch + ch * 16);
        }
        #pragma unroll
        for (int i = 0; i < 2; ++i) {                  // Bl
            int l = tid + (i << 9);
            int r = l >> 3, ch = l & 7;
            uint32_t off = (uint32_t)(r * 128 + ch * 16);
            cp16(st + 81920 + swz(off), bl_ + (size_t)r * pitch + ch * 16);
        }
    };

    const int a_row = wm * 32 + (lane & 15);
    const int a_kc  = (lane >> 4);
    const int b_row = wn * 64 + (lane & 7) + ((lane >> 4) & 1) * 8;
    const int b_kc  = ((lane >> 3) & 1);

    load_stage(0, 0);
    CP_COMMIT();

    for (int it = 0; it < 32; ++it) {
        const int buf = it & 1;
        if (it + 1 < 32) {
            load_stage(1 - buf, it + 1);
            CP_COMMIT();
            cp_wait<1>();
        } else {
            cp_wait<0>();
        }
        __syncthreads();

        const uint32_t stb = sb + (uint32_t)buf * SED_STAGE;
        const uint32_t bAh = stb;
        const uint32_t bAl = stb + 32768;
        const uint32_t bBh = stb + 65536;
        const uint32_t bBl = stb + 81920;

        #pragma unroll
        for (int ks = 0; ks < 4; ++ks) {
            uint32_t ah[2][4], al[2][4], bh[4][4], bl[4][4];
            #pragma unroll
            for (int mt = 0; mt < 2; ++mt) {
                uint32_t off = swz((uint32_t)((a_row + mt * 16) * 128
                                              + (a_kc + 2 * ks) * 16));
                ldsm_x4(bAh + off, ah[mt]);
                ldsm_x4(bAl + off, al[mt]);
            }
            #pragma unroll
            for (int nt = 0; nt < 4; ++nt) {
                uint32_t off = swz((uint32_t)((b_row + nt * 16) * 128
                                              + (b_kc + 2 * ks) * 16));
                ldsm_x4(bBh + off, bh[nt]);
                ldsm_x4(bBl + off, bl[nt]);
            }
            #pragma unroll
            for (int mt = 0; mt < 2; ++mt)
                #pragma unroll
                for (int nt = 0; nt < 8; ++nt) {
                    const uint32_t* bfh = &bh[nt >> 1][(nt & 1) * 2];
                    const uint32_t* bfl = &bl[nt >> 1][(nt & 1) * 2];
                    mma16816(acc[mt][nt], ah[mt], bfh);
                    mma16816(acc[mt][nt], ah[mt], bfl);
                    mma16816(acc[mt][nt], al[mt], bfh);
                }
        }
        __syncthreads();
    }

    // epilogue: gelu -> split bf16
    #pragma unroll
    for (int mt = 0; mt < 2; ++mt) {
        const int row0 = mrow0 + wm * 32 + mt * 16 + (lane >> 2);
        #pragma unroll
        for (int nt = 0; nt < 8; ++nt) {
            const int col = n0 + wn * 64 + nt * 8 + (lane & 3) * 2;
            float v[4] = { acc[mt][nt][0], acc[mt][nt][1],
                           acc[mt][nt][2], acc[mt][nt][3] };
            #pragma unroll
            for (int q = 0; q < 4; ++q) v[q] = gelu_exact(v[q]);
            const size_t o0 = (size_t)row0 * 2048 + col;
            const size_t o1 = (size_t)(row0 + 8) * 2048 + col;
            __nv_bfloat16 h0, l0, h1, l1;
            split_bf16(v[0], h0, l0); split_bf16(v[1], h1, l1);
            *(__nv_bfloat162*)(outh + o0) = __halves2bfloat162(h0, h1);
            *(__nv_bfloat162*)(outl + o0) = __halves2bfloat162(l0, l1);
            split_bf16(v[2], h0, l0); split_bf16(v[3], h1, l1);
            *(__nv_bfloat162*)(outh + o1) = __halves2bfloat162(h0, h1);
            *(__nv_bfloat162*)(outl + o1) = __halves2bfloat162(l0, l1);
        }
    }
}

// ---------------------------------------------------------------------------
// Shared 128x128 mainloop (8 warps, warp 32x64) as a device function.
// ---------------------------------------------------------------------------
static constexpr int TILE_B = 16384;
static constexpr int GEN_SMEM = 8 * TILE_B;     // 128 KB

template<int KITERS>
__device__ __forceinline__ void gemm128_mainloop(
        uint32_t sb, int tid, int wid, int lane,
        const char* sAh, const char* sAl, const char* sBh, const char* sBl,
        size_t pitch, float acc[2][8][4]) {
    const int wm = wid & 3, wn = wid >> 2;

    auto load_stage = [&](int stage, int kt) {
        const char* src[4] = { sAh + (size_t)kt * 128, sAl + (size_t)kt * 128,
                               sBh + (size_t)kt * 128, sBl + (size_t)kt * 128 };
        #pragma unroll
        for (int t = 0; t < 4; ++t) {
            uint32_t tb = sb + (uint32_t)(stage * 4 + t) * TILE_B;
            #pragma unroll
            for (int i = 0; i < 4; ++i) {
                int l = tid + (i << 8);
                int r = l >> 3, ch = l & 7;
                uint32_t off = (uint32_t)(r * 128 + ch * 16);
                cp16(tb + swz(off), src[t] + (size_t)r * pitch + ch * 16);
            }
        }
    };

    const int a_row = wm * 32 + (lane & 15);
    const int a_kc  = (lane >> 4);
    const int b_row = wn * 64 + (lane & 7) + ((lane >> 4) & 1) * 8;
    const int b_kc  = ((lane >> 3) & 1);

    load_stage(0, 0);
    CP_COMMIT();

    for (int it = 0; it < KITERS; ++it) {
        const int buf = it & 1;
        if (it + 1 < KITERS) {
            load_stage(1 - buf, it + 1);
            CP_COMMIT();
            cp_wait<1>();
        } else {
            cp_wait<0>();
        }
        __syncthreads();

        const uint32_t bAh = sb + (uint32_t)(buf * 4 + 0) * TILE_B;
        const uint32_t bAl = sb + (uint32_t)(buf * 4 + 1) * TILE_B;
        const uint32_t bBh = sb + (uint32_t)(buf * 4 + 2) * TILE_B;
        const uint32_t bBl = sb + (uint32_t)(buf * 4 + 3) * TILE_B;

        #pragma unroll
        for (int ks = 0; ks < 4; ++ks) {
            uint32_t ah[2][4], al[2][4], bh[4][4], bl[4][4];
            #pragma unroll
            for (int mt = 0; mt < 2; ++mt) {
                uint32_t off = swz((uint32_t)((a_row + mt * 16) * 128
                                              + (a_kc + 2 * ks) * 16));
                ldsm_x4(bAh + off, ah[mt]);
                ldsm_x4(bAl + off, al[mt]);
            }
            #pragma unroll
            for (int nt = 0; nt < 4; ++nt) {
                uint32_t off = swz((uint32_t)((b_row + nt * 16) * 128
                                              + (b_kc + 2 * ks) * 16));
                ldsm_x4(bBh + off, bh[nt]);
                ldsm_x4(bBl + off, bl[nt]);
            }
            #pragma unroll
            for (int mt = 0; mt < 2; ++mt)
                #pragma unroll
                for (int nt = 0; nt < 8; ++nt) {
                    const uint32_t* bfh = &bh[nt >> 1][(nt & 1) * 2];
                    const uint32_t* bfl = &bl[nt >> 1][(nt & 1) * 2];
                    mma16816(acc[mt][nt], ah[mt], bfh);
                    mma16816(acc[mt][nt], ah[mt], bfl);
                    mma16816(acc[mt][nt], al[mt], bfh);
                }
        }
        __syncthreads();
    }
}

// ---------------------------------------------------------------------------
// proj GEMM + bias + residual + FUSED LN2 -> y fp32, yn hi/lo bf16
// grid (1, 1024): CTA owns complete 128-channel rows.
// ---------------------------------------------------------------------------
__global__ void __launch_bounds__(256, 1)
k_proj(const __nv_bfloat16* __restrict__ Ah, const __nv_bfloat16* __restrict__ Al,
       const __nv_bfloat16* __restrict__ Bh, const __nv_bfloat16* __restrict__ Bl,
       const float* __restrict__ bias, const float* __restrict__ add,
       const float* __restrict__ g2, const float* __restrict__ b2,
       float* __restrict__ y,
       __nv_bfloat16* __restrict__ ynh, __nv_bfloat16* __restrict__ ynl) {
    extern __shared__ __align__(1024) char smem[];
    const uint32_t sb = smem_u32(smem);
    const int tid = threadIdx.x, wid = tid >> 5, lane = tid & 31;
    const int wm = wid & 3, wn = wid >> 2;
    const int mrow0 = blockIdx.y * 128;

    float acc[2][8][4];
    #pragma unroll
    for (int mt = 0; mt < 2; ++mt)
        #pragma unroll
        for (int nt = 0; nt < 8; ++nt)
            #pragma unroll
            for (int q = 0; q < 4; ++q) acc[mt][nt][q] = 0.f;

    gemm128_mainloop<2>(sb, tid, wid, lane,
        (const char*)Ah + (size_t)mrow0 * 256,
        (const char*)Al + (size_t)mrow0 * 256,
        (const char*)Bh, (const char*)Bl, 256, acc);

    // pass 1: bias + residual, write y, accumulate row sums
    float s_loc[2][2] = {{0.f,0.f},{0.f,0.f}};
    float q_loc[2][2] = {{0.f,0.f},{0.f,0.f}};
    #pragma unroll
    for (int mt = 0; mt < 2; ++mt) {
        const int r0 = mrow0 + wm * 32 + mt * 16 + (lane >> 2);
        #pragma unroll
        for (int nt = 0; nt < 8; ++nt) {
            const int col = wn * 64 + nt * 8 + (lane & 3) * 2;
            float bb0 = __ldg(&bias[col]), bb1 = __ldg(&bias[col + 1]);
            const size_t o0 = (size_t)r0 * 128 + col;
            const size_t o1 = (size_t)(r0 + 8) * 128 + col;
            float2 a0 = *(const float2*)(add + o0);
            float2 a1 = *(const float2*)(add + o1);
            float v0 = acc[mt][nt][0] + bb0 + a0.x;
            float v1 = acc[mt][nt][1] + bb1 + a0.y;
            float v2 = acc[mt][nt][2] + bb0 + a1.x;
            float v3 = acc[mt][nt][3] + bb1 + a1.y;
            *(float2*)(y + o0) = make_float2(v0, v1);
            *(float2*)(y + o1) = make_float2(v2, v3);
            acc[mt][nt][0] = v0; acc[mt][nt][1] = v1;
            acc[mt][nt][2] = v2; acc[mt][nt][3] = v3;
            s_loc[mt][0] += v0 + v1; q_loc[mt][0] += v0 * v0 + v1 * v1;
            s_loc[mt][1] += v2 + v3; q_loc[mt][1] += v2 * v2 + v3 * v3;
        }
    }
    // reduce over the 4 lanes sharing a row
    #pragma unroll
    for (int mt = 0; mt < 2; ++mt)
        #pragma unroll
        for (int h = 0; h < 2; ++h) {
            float s = s_loc[mt][h], q = q_loc[mt][h];
            s += __shfl_xor_sync(0xffffffffu, s, 1);
            s += __shfl_xor_sync(0xffffffffu, s, 2);
            q += __shfl_xor_sync(0xffffffffu, q, 1);
            q += __shfl_xor_sync(0xffffffffu, q, 2);
            s_loc[mt][h] = s; q_loc[mt][h] = q;
        }
    float* rsum = (float*)smem;            // [128][2]
    float* rsq  = rsum + 256;
    if ((lane & 3) == 0) {
        #pragma unroll
        for (int mt = 0; mt < 2; ++mt)
            #pragma unroll
            for (int h = 0; h < 2; ++h) {
                int rl = wm * 32 + mt * 16 + h * 8 + (lane >> 2);
                rsum[rl * 2 + wn] = s_loc[mt][h];
                rsq [rl * 2 + wn] = q_loc[mt][h];
            }
    }
    __syncthreads();

    // pass 2: LN2 normalize + split bf16 out
    #pragma unroll
    for (int mt = 0; mt < 2; ++mt) {
        const int rl0 = wm * 32 + mt * 16 + (lane >> 2);
        const int rl1 = rl0 + 8;
        float S0 = rsum[rl0 * 2] + rsum[rl0 * 2 + 1];
        float Q0 = rsq [rl0 * 2] + rsq [rl0 * 2 + 1];
        float S1 = rsum[rl1 * 2] + rsum[rl1 * 2 + 1];
        float Q1 = rsq [rl1 * 2] + rsq [rl1 * 2 + 1];
        float mu0 = S0 * (1.0f / 128.0f);
        float rs0 = rsqrtf(Q0 * (1.0f / 128.0f) - mu0 * mu0 + 1e-5f);
        float mu1 = S1 * (1.0f / 128.0f);
        float rs1 = rsqrtf(Q1 * (1.0f / 128.0f) - mu1 * mu1 + 1e-5f);
        const int r0 = mrow0 + rl0;
        #pragma unroll
        for (int nt = 0; nt < 8; ++nt) {
            const int col = wn * 64 + nt * 8 + (lane & 3) * 2;
            float g0 = __ldg(&g2[col]), g1 = __ldg(&g2[col + 1]);
            float be0 = __ldg(&b2[col]), be1 = __ldg(&b2[col + 1]);
            float n0 = (acc[mt][nt][0] - mu0) * rs0 * g0 + be0;
            float n1 = (acc[mt][nt][1] - mu0) * rs0 * g1 + be1;
            float n2 = (acc[mt][nt][2] - mu1) * rs1 * g0 + be0;
            float n3 = (acc[mt][nt][3] - mu1) * rs1 * g1 + be1;
            const size_t o0 = (size_t)r0 * 128 + col;
            const size_t o1 = (size_t)(r0 + 8) * 128 + col;
            __nv_bfloat16 h0, l0, h1, l1;
            split_bf16(n0, h0, l0); split_bf16(n1, h1, l1);
            *(__nv_bfloat162*)(ynh + o0) = __halves2bfloat162(h0, h1);
            *(__nv_bfloat162*)(ynl + o0) = __halves2bfloat162(l0, l1);
            split_bf16(n2, h0, l0); split_bf16(n3, h1, l1);
            *(__nv_bfloat162*)(ynh + o1) = __halves2bfloat162(h0, h1);
            *(__nv_bfloat162*)(ynl + o1) = __halves2bfloat162(l0, l1);
        }
    }
}

// ---------------------------------------------------------------------------
// MLP1: GEMM + bias + gelu -> h hi/lo bf16.  grid (4, 1024).
// ---------------------------------------------------------------------------
__global__ void __launch_bounds__(256, 1)
k_mlp1(const __nv_bfloat16* __restrict__ Ah, const __nv_bfloat16* __restrict__ Al,
       const __nv_bfloat16* __restrict__ Bh, const __nv_bfloat16* __restrict__ Bl,
       const float* __restrict__ bias,
       __nv_bfloat16* __restrict__ outh, __nv_bfloat16* __restrict__ outl) {
    extern __shared__ __align__(1024) char smem[];
    const uint32_t sb = smem_u32(smem);
    const int tid = threadIdx.x, wid = tid >> 5, lane = tid & 31;
    const int wm = wid & 3, wn = wid >> 2;
    const int mrow0 = blockIdx.y * 128;
    const int n0    = blockIdx.x * 128;

    float acc[2][8][4];
    #pragma unroll
    for (int mt = 0; mt < 2; ++mt)
        #pragma unroll
        for (int nt = 0; nt < 8; ++nt)
            #pragma unroll
            for (int q = 0; q < 4; ++q) acc[mt][nt][q] = 0.f;

    gemm128_mainloop<2>(sb, tid, wid, lane,
        (const char*)Ah + (size_t)mrow0 * 256,
        (const char*)Al + (size_t)mrow0 * 256,
        (const char*)Bh + (size_t)n0 * 256,
        (const char*)Bl + (size_t)n0 * 256, 256, acc);

    #pragma unroll
    for (int mt = 0; mt < 2; ++mt) {
        const int row0 = mrow0 + wm * 32 + mt * 16 + (lane >> 2);
        #pragma unroll
        for (int nt = 0; nt < 8; ++nt) {
            const int col = n0 + wn * 64 + nt * 8 + (lane & 3) * 2;
            float bb0 = __ldg(&bias[col]), bb1 = __ldg(&bias[col + 1]);
            float v0 = gelu_exact(acc[mt][nt][0] + bb0);
            float v1 = gelu_exact(acc[mt][nt][1] + bb1);
            float v2 = gelu_exact(acc[mt][nt][2] + bb0);
            float v3 = gelu_exact(acc[mt][nt][3] + bb1);
            const size_t o0 = (size_t)row0 * 512 + col;
            const size_t o1 = (size_t)(row0 + 8) * 512 + col;
            __nv_bfloat16 h0, l0, h1, l1;
            split_bf16(v0, h0, l0); split_bf16(v1, h1, l1);
            *(__nv_bfloat162*)(outh + o0) = __halves2bfloat162(h0, h1);
            *(__nv_bfloat162*)(outl + o0) = __halves2bfloat162(l0, l1);
            split_bf16(v2, h0, l0); split_bf16(v3, h1, l1);
            *(__nv_bfloat162*)(outh + o1) = __halves2bfloat162(h0, h1);
            *(__nv_bfloat162*)(outl + o1) = __halves2bfloat162(l0, l1);
        }
    }
}

// ---------------------------------------------------------------------------
// MLP2: GEMM + bias + residual, FUSED window->NCHW transpose out. grid (1,1024)
// CTA rows = 8 aligned windows: b fixed, h4 fixed, w4 in [w40, w40+8).
// ---------------------------------------------------------------------------
__global__ void __launch_bounds__(256, 1)
k_mlp2(const __nv_bfloat16* __restrict__ Ah, const __nv_bfloat16* __restrict__ Al,
       const __nv_bfloat16* __restrict__ Bh, const __nv_bfloat16* __restrict__ Bl,
       const float* __restrict__ bias, const float* __restrict__ add,
       float* __restrict__ out) {
    extern __shared__ __align__(1024) char smem[];
    const uint32_t sb = smem_u32(smem);
    const int tid = threadIdx.x, wid = tid >> 5, lane = tid & 31;
    const int wm = wid & 3, wn = wid >> 2;
    const int mrow0 = blockIdx.y * 128;

    float acc[2][8][4];
    #pragma unroll
    for (int mt = 0; mt < 2; ++mt)
        #pragma unroll
        for (int nt = 0; nt < 8; ++nt)
            #pragma unroll
            for (int q = 0; q < 4; ++q) acc[mt][nt][q] = 0.f;

    gemm128_mainloop<8>(sb, tid, wid, lane,
        (const char*)Ah + (size_t)mrow0 * 1024,
        (const char*)Al + (size_t)mrow0 * 1024,
        (const char*)Bh, (const char*)Bl, 1024, acc);

    // stage into smem [row][col], pitch 132 floats
    float* stg = (float*)smem;
    #pragma unroll
    for (int mt = 0; mt < 2; ++mt) {
        const int rl = wm * 32 + mt * 16 + (lane >> 2);
        #pragma unroll
        for (int nt = 0; nt < 8; ++nt) {
            const int col = wn * 64 + nt * 8 + (lane & 3) * 2;
            float bb0 = __ldg(&bias[col]), bb1 = __ldg(&bias[col + 1]);
            const size_t o0 = (size_t)(mrow0 + rl) * 128 + col;
            const size_t o1 = (size_t)(mrow0 + rl + 8) * 128 + col;
            float2 a0 = *(const float2*)(add + o0);
            float2 a1 = *(const float2*)(add + o1);
            stg[rl * 132 + col]           = acc[mt][nt][0] + bb0 + a0.x;
            stg[rl * 132 + col + 1]       = acc[mt][nt][1] + bb1 + a0.y;
            stg[(rl + 8) * 132 + col]     = acc[mt][nt][2] + bb0 + a1.x;
            stg[(rl + 8) * 132 + col + 1] = acc[mt][nt][3] + bb1 + a1.y;
        }
    }
    __syncthreads();

    // coalesced NCHW writeout: warp per (c, hh) segment of 32 w
    const int widx0 = blockIdx.y * 8;
    const int b   = widx0 >> 10;
    const int h4  = (widx0 >> 5) & 31;
    const int w40 = widx0 & 31;
    for (int seg = wid; seg < 512; seg += 8) {
        int c = seg >> 2, hh = seg & 3;
        int row = ((lane >> 2) << 4) + (hh << 2) + (lane & 3);
        float val = stg[row * 132 + c];
        out[(((size_t)(b * 128 + c)) * 128 + h4 * 4 + hh) * 128
            + w40 * 4 + lane] = val;
    }
}

// ---------------------------------------------------------------------------
// Launch
// ---------------------------------------------------------------------------
extern "C" void kernel_launch(void* const* d_in, const int* in_sizes, int n_in,
                              void* d_out, int out_size) {
    const float* x      = (const float*)d_in[0];
    const float* gamma1 = (const float*)d_in[1];
    const float* beta1  = (const float*)d_in[2];
    const float* sed_w  = (const float*)d_in[3];
    const float* w_proj = (const float*)d_in[4];
    const float* b_proj = (const float*)d_in[5];
    const float* gamma2 = (const float*)d_in[6];
    const float* beta2  = (const float*)d_in[7];
    const float* w1     = (const float*)d_in[8];
    const float* b1     = (const float*)d_in[9];
    const float* w2     = (const float*)d_in[10];
    const float* b2     = (const float*)d_in[11];
    float* out = (float*)d_out;

    float *xt, *y;
    __nv_bfloat16 *xnh, *xnl, *gh, *gl, *ynh, *ynl, *hh, *hl;
    __nv_bfloat16 *bth, *btl, *bph, *bpl, *b1h, *b1l, *b2h, *b2l;
    cudaGetSymbolAddress((void**)&xt,  g_xt);
    cudaGetSymbolAddress((void**)&y,   g_y);
    cudaGetSymbolAddress((void**)&xnh, g_xnh);
    cudaGetSymbolAddress((void**)&xnl, g_xnl);
    cudaGetSymbolAddress((void**)&gh,  g_gh);
    cudaGetSymbolAddress((void**)&gl,  g_gl);
    cudaGetSymbolAddress((void**)&ynh, g_ynh);
    cudaGetSymbolAddress((void**)&ynl, g_ynl);
    cudaGetSymbolAddress((void**)&hh,  g_hh);
    cudaGetSymbolAddress((void**)&hl,  g_hl);
    cudaGetSymbolAddress((void**)&bth, g_bth);
    cudaGetSymbolAddress((void**)&btl, g_btl);
    cudaGetSymbolAddress((void**)&bph, g_bph);
    cudaGetSymbolAddress((void**)&bpl, g_bpl);
    cudaGetSymbolAddress((void**)&b1h, g_b1h);
    cudaGetSymbolAddress((void**)&b1l, g_b1l);
    cudaGetSymbolAddress((void**)&b2h, g_b2h);
    cudaGetSymbolAddress((void**)&b2l, g_b2l);

    cudaFuncSetAttribute(k_sed,  cudaFuncAttributeMaxDynamicSharedMemorySize, SED_SMEM);
    cudaFuncSetAttribute(k_proj, cudaFuncAttributeMaxDynamicSharedMemorySize, GEN_SMEM);
    cudaFuncSetAttribute(k_mlp1, cudaFuncAttributeMaxDynamicSharedMemorySize, GEN_SMEM);
    cudaFuncSetAttribute(k_mlp2, cudaFuncAttributeMaxDynamicSharedMemorySize, GEN_SMEM);

    // weight preps
    k_prep_sed<<<2048, 128>>>(sed_w, bth, btl);
    k_prep_w<<<128, 128>>>(w_proj, 128, 128, bph, bpl);
    k_prep_w<<<512, 128>>>(w1, 128, 512, b1h, b1l);
    k_prep_w<<<128, 128>>>(w2, 512, 128, b2h, b2l);

    // 1) LN1 + transpose
    k_ln1<<<dim3(512, 8), 256>>>(x, gamma1, beta1, xt, xnh, xnl);

    // 2) SED: [8192 x 2048] @ Wbig^T, gelu
    k_sed<<<dim3(16, 32), 512, SED_SMEM>>>(xnh, xnl, bth, btl, gh, gl);

    // 3) proj + residual + fused LN2
    k_proj<<<dim3(1, 1024), 256, GEN_SMEM>>>(
        gh, gl, bph, bpl, b_proj, xt, gamma2, beta2, y, ynh, ynl);

    // 4) MLP1: + b1, gelu
    k_mlp1<<<dim3(4, 1024), 256, GEN_SMEM>>>(
        ynh, ynl, b1h, b1l, b1, hh, hl);

    // 5) MLP2: + b2 + y, fused NCHW writeout
    k_mlp2<<<dim3(1, 1024), 256, GEN_SMEM>>>(
        hh, hl, b2h, b2l, b2, y, out);
}

// round 5
// speedup vs baseline: 1.0565x; 1.0565x over previous
#include <cuda_runtime.h>
#include <cuda_bf16.h>
#include <cstdint>
#include <cstddef>

// ---------------------------------------------------------------------------
// Cayley-Dickson sign table:  e_i * e_j = sign(i,j) * e_{i XOR j}
// ---------------------------------------------------------------------------
constexpr int cdsign(int i, int j, int n) {
    return (n == 1) ? 1
         : (i < n/2 && j < n/2) ? cdsign(i, j, n/2)
         : (i < n/2)            ? cdsign(j - n/2, i, n/2)
         : (j < n/2)            ? cdsign(i - n/2, j, n/2) * (j == 0 ? 1 : -1)
         : -cdsign(j - n/2, i - n/2, n/2) * ((j - n/2) == 0 ? 1 : -1);
}
struct SgnTab { signed char v[16][16]; };
constexpr SgnTab make_sgn() {
    SgnTab t{};
    for (int i = 0; i < 16; ++i)
        for (int j = 0; j < 16; ++j)
            t.v[i][j] = (signed char)cdsign(i, j, 16);
    return t;
}
__constant__ SgnTab c_SGN = make_sgn();

// ---------------------------------------------------------------------------
static constexpr int C = 128, NPIX = 8 * 128 * 128;   // 131072
static constexpr int CH = 512;

// fp32 buffers
__device__ float g_xt[NPIX * C];
__device__ float g_y [NPIX * C];

// bf16 split operand buffers
__device__ __align__(256) __nv_bfloat16 g_xnh[NPIX * C];
__device__ __align__(256) __nv_bfloat16 g_xnl[NPIX * C];
__device__ __align__(256) __nv_bfloat16 g_gh [NPIX * C];
__device__ __align__(256) __nv_bfloat16 g_gl [NPIX * C];
__device__ __align__(256) __nv_bfloat16 g_ynh[NPIX * C];
__device__ __align__(256) __nv_bfloat16 g_ynl[NPIX * C];
__device__ __align__(256) __nv_bfloat16 g_hh [NPIX * CH];
__device__ __align__(256) __nv_bfloat16 g_hl [NPIX * CH];
// weight (B^T, n-major rows of K) buffers
__device__ __align__(256) __nv_bfloat16 g_bth[2048 * 2048];
__device__ __align__(256) __nv_bfloat16 g_btl[2048 * 2048];
__device__ __align__(256) __nv_bfloat16 g_bph[128 * 128];
__device__ __align__(256) __nv_bfloat16 g_bpl[128 * 128];
__device__ __align__(256) __nv_bfloat16 g_b1h[512 * 128];
__device__ __align__(256) __nv_bfloat16 g_b1l[512 * 128];
__device__ __align__(256) __nv_bfloat16 g_b2h[128 * 512];
__device__ __align__(256) __nv_bfloat16 g_b2l[128 * 512];

// ---------------------------------------------------------------------------
// PTX helpers (sm_80-compatible: cp.async, ldmatrix, mma.sync)
// ---------------------------------------------------------------------------
__device__ __forceinline__ uint32_t smem_u32(const void* p) {
    uint32_t a;
    asm("{ .reg .u64 t; cvta.to.shared.u64 t, %1; cvt.u32.u64 %0, t; }"
        : "=r"(a) : "l"(p));
    return a;
}
__device__ __forceinline__ void cp16(uint32_t dst, const void* src) {
    asm volatile("cp.async.cg.shared.global [%0], [%1], 16;" :: "r"(dst), "l"(src));
}
#define CP_COMMIT() asm volatile("cp.async.commit_group;" ::: "memory")
template<int N>
__device__ __forceinline__ void cp_wait() {
    asm volatile("cp.async.wait_group %0;" :: "n"(N) : "memory");
}
__device__ __forceinline__ void ldsm_x4(uint32_t addr, uint32_t* r) {
    asm volatile("ldmatrix.sync.aligned.m8n8.x4.shared.b16 {%0,%1,%2,%3}, [%4];"
        : "=r"(r[0]), "=r"(r[1]), "=r"(r[2]), "=r"(r[3]) : "r"(addr));
}
__device__ __forceinline__ void mma16816(float* c, const uint32_t* a, const uint32_t* b) {
    asm volatile("mma.sync.aligned.m16n8k16.row.col.f32.bf16.bf16.f32 "
        "{%0,%1,%2,%3}, {%4,%5,%6,%7}, {%8,%9}, {%0,%1,%2,%3};"
        : "+f"(c[0]), "+f"(c[1]), "+f"(c[2]), "+f"(c[3])
        : "r"(a[0]), "r"(a[1]), "r"(a[2]), "r"(a[3]), "r"(b[0]), "r"(b[1]));
}
__device__ __forceinline__ uint32_t swz(uint32_t off) {
    return off ^ ((off >> 3) & 0x70);
}
__device__ __forceinline__ float gelu_exact(float v) {
    return 0.5f * v * (1.0f + erff(v * 0.7071067811865476f));
}
__device__ __forceinline__ void split_bf16(float v, __nv_bfloat16& h, __nv_bfloat16& l) {
    h = __float2bfloat16_rn(v);
    l = __float2bfloat16_rn(v - __bfloat162float(h));
}

// ---------------------------------------------------------------------------
// LN1 + NCHW -> window-major (writes xt fp32 and xn hi/lo bf16)
// ---------------------------------------------------------------------------
__global__ void k_ln1(const float* __restrict__ x,
                      const float* __restrict__ g1,
                      const float* __restrict__ b1,
                      float* __restrict__ xt,
                      __nv_bfloat16* __restrict__ xnh,
                      __nv_bfloat16* __restrict__ xnl) {
    __shared__ float sh[128][33];
    __shared__ float red[2][8][32];
    __shared__ float smean[32], srstd[32];

    const int b  = blockIdx.y;
    const int s0 = blockIdx.x * 32;
    const int tp = threadIdx.x & 31;
    const int ty = threadIdx.x >> 5;

    const float* xb = x + (size_t)b * 128 * 16384 + s0;
    float sum = 0.f, sq = 0.f;
    #pragma unroll
    for (int c0 = 0; c0 < 128; c0 += 8) {
        int c = c0 + ty;
        float v = xb[(size_t)c * 16384 + tp];
        sh[c][tp] = v;
        sum += v; sq += v * v;
    }
    red[0][ty][tp] = sum; red[1][ty][tp] = sq;
    __syncthreads();
    if (ty == 0) {
        float s = 0.f, q = 0.f;
        #pragma unroll
        for (int y = 0; y < 8; ++y) { s += red[0][y][tp]; q += red[1][y][tp]; }
        float m = s * (1.0f / 128.0f);
        smean[tp] = m;
        srstd[tp] = rsqrtf(q * (1.0f / 128.0f) - m * m + 1e-5f);
    }
    __syncthreads();

    for (int l = threadIdx.x; l < 32 * 128; l += 256) {
        int p = l >> 7, c = l & 127;
        int s = s0 + p;
        int hh = s >> 7, ww = s & 127;
        int row = ((((b * 32 + (hh >> 2)) * 32 + (ww >> 2)) << 4)
                  + ((hh & 3) << 2) + (ww & 3));
        float v = sh[c][p];
        size_t idx = (size_t)row * 128 + c;
        xt[idx] = v;
        float nv = (v - smean[p]) * srstd[p] * g1[c] + b1[c];
        __nv_bfloat16 h, lo; split_bf16(nv, h, lo);
        xnh[idx] = h; xnl[idx] = lo;
    }
}

// ---------------------------------------------------------------------------
// Weight preps
// ---------------------------------------------------------------------------
__global__ void k_prep_sed(const float* __restrict__ sed_w,
                           __nv_bfloat16* __restrict__ bh,
                           __nv_bfloat16* __restrict__ bl) {
    int n = blockIdx.x;
    int nblk = n >> 7, d = n & 127;
    for (int k = threadIdx.x; k < 2048; k += 128) {
        int i = k >> 7, c = k & 127;
        int j = i ^ nblk;
        float s = (float)c_SGN.v[i][j];
        float v = s * __ldg(&sed_w[(size_t)(j * 128 + c) * 128 + d]);
        __nv_bfloat16 h, lo; split_bf16(v, h, lo);
        size_t idx = (size_t)n * 2048 + k;
        bh[idx] = h; bl[idx] = lo;
    }
}

__global__ void k_prep_w(const float* __restrict__ W, int K, int N,
                         __nv_bfloat16* __restrict__ bh,
                         __nv_bfloat16* __restrict__ bl) {
    int n = blockIdx.x;
    for (int k = threadIdx.x; k < K; k += 128) {
        float v = __ldg(&W[(size_t)k * N + n]);
        __nv_bfloat16 h, lo; split_bf16(v, h, lo);
        size_t idx = (size_t)n * K + k;
        bh[idx] = h; bl[idx] = lo;
    }
}

// ---------------------------------------------------------------------------
// Shared 128x128 mainloop (8 warps, warp 32x64), STAGES-deep cp.async pipe,
// ONE __syncthreads per K64 iteration.
// D = Ah*Bh + Ah*Bl + Al*Bh (fp32 accum).
// ---------------------------------------------------------------------------
static constexpr int TILE_B = 16384;

template<int KITERS, int STAGES>
__device__ __forceinline__ void gemm128_mainloop(
        uint32_t sb, int tid, int wid, int lane,
        const char* sAh, const char* sAl, const char* sBh, const char* sBl,
        size_t pitch, float acc[2][8][4]) {
    const int wm = wid & 3, wn = wid >> 2;

    auto load_stage = [&](int stage, int kt) {
        const char* src[4] = { sAh + (size_t)kt * 128, sAl + (size_t)kt * 128,
                               sBh + (size_t)kt * 128, sBl + (size_t)kt * 128 };
        #pragma unroll
        for (int t = 0; t < 4; ++t) {
            uint32_t tb = sb + (uint32_t)(stage * 4 + t) * TILE_B;
            #pragma unroll
            for (int i = 0; i < 4; ++i) {
                int l = tid + (i << 8);
                int r = l >> 3, ch = l & 7;
                uint32_t off = (uint32_t)(r * 128 + ch * 16);
                cp16(tb + swz(off), src[t] + (size_t)r * pitch + ch * 16);
            }
        }
    };

    const int a_row = wm * 32 + (lane & 15);
    const int a_kc  = (lane >> 4);
    const int b_row = wn * 64 + (lane & 7) + ((lane >> 4) & 1) * 8;
    const int b_kc  = ((lane >> 3) & 1);

    #pragma unroll
    for (int s = 0; s < STAGES - 1 && s < KITERS; ++s) {
        load_stage(s, s);
        CP_COMMIT();
    }

    for (int it = 0; it < KITERS; ++it) {
        cp_wait<STAGES - 2>();      // stage `it` resident
        __syncthreads();            // all consumers of slot (it-1)%S passed

        // prefetch stage it+S-1 into slot (it+S-1)%S == (it-1)%S
        if (it + STAGES - 1 < KITERS)
            load_stage((it + STAGES - 1) % STAGES, it + STAGES - 1);
        CP_COMMIT();                // commit every iter: uniform accounting

        const int buf = it % STAGES;
        const uint32_t bAh = sb + (uint32_t)(buf * 4 + 0) * TILE_B;
        const uint32_t bAl = sb + (uint32_t)(buf * 4 + 1) * TILE_B;
        const uint32_t bBh = sb + (uint32_t)(buf * 4 + 2) * TILE_B;
        const uint32_t bBl = sb + (uint32_t)(buf * 4 + 3) * TILE_B;

        #pragma unroll
        for (int ks = 0; ks < 4; ++ks) {
            uint32_t ah[2][4], al[2][4], bh[4][4], bl[4][4];
            #pragma unroll
            for (int mt = 0; mt < 2; ++mt) {
                uint32_t off = swz((uint32_t)((a_row + mt * 16) * 128
                                              + (a_kc + 2 * ks) * 16));
                ldsm_x4(bAh + off, ah[mt]);
                ldsm_x4(bAl + off, al[mt]);
            }
            #pragma unroll
            for (int nt = 0; nt < 4; ++nt) {
                uint32_t off = swz((uint32_t)((b_row + nt * 16) * 128
                                              + (b_kc + 2 * ks) * 16));
                ldsm_x4(bBh + off, bh[nt]);
                ldsm_x4(bBl + off, bl[nt]);
            }
            #pragma unroll
            for (int mt = 0; mt < 2; ++mt)
                #pragma unroll
                for (int nt = 0; nt < 8; ++nt) {
                    const uint32_t* bfh = &bh[nt >> 1][(nt & 1) * 2];
                    const uint32_t* bfl = &bl[nt >> 1][(nt & 1) * 2];
                    mma16816(acc[mt][nt], ah[mt], bfh);
                    mma16816(acc[mt][nt], ah[mt], bfl);
                    mma16816(acc[mt][nt], al[mt], bfh);
                }
        }
    }
}

#define ACC_INIT(acc)                                  \
    _Pragma("unroll")                                  \
    for (int mt = 0; mt < 2; ++mt)                     \
        _Pragma("unroll")                              \
        for (int nt = 0; nt < 8; ++nt)                 \
            _Pragma("unroll")                          \
            for (int q = 0; q < 4; ++q) acc[mt][nt][q] = 0.f;

// ---------------------------------------------------------------------------
// SED: [8192 x 2048] @ Wbig^T, K=2048 (32 iters, 3 stages), gelu -> bf16 hi/lo
// ---------------------------------------------------------------------------
static constexpr int SED_SMEM = 3 * 4 * TILE_B;    // 192 KB

__global__ void __launch_bounds__(256, 1)
k_sed(const __nv_bfloat16* __restrict__ Ah, const __nv_bfloat16* __restrict__ Al,
      const __nv_bfloat16* __restrict__ Bh, const __nv_bfloat16* __restrict__ Bl,
      __nv_bfloat16* __restrict__ outh, __nv_bfloat16* __restrict__ outl) {
    extern __shared__ __align__(1024) char smem[];
    const uint32_t sb = smem_u32(smem);
    const int tid = threadIdx.x, wid = tid >> 5, lane = tid & 31;
    const int wm = wid & 3, wn = wid >> 2;
    const int mrow0 = blockIdx.y * 128;
    const int n0    = blockIdx.x * 128;

    float acc[2][8][4];
    ACC_INIT(acc);

    gemm128_mainloop<32, 3>(sb, tid, wid, lane,
        (const char*)Ah + (size_t)mrow0 * 4096,
        (const char*)Al + (size_t)mrow0 * 4096,
        (const char*)Bh + (size_t)n0 * 4096,
        (const char*)Bl + (size_t)n0 * 4096, 4096, acc);

    #pragma unroll
    for (int mt = 0; mt < 2; ++mt) {
        const int row0 = mrow0 + wm * 32 + mt * 16 + (lane >> 2);
        #pragma unroll
        for (int nt = 0; nt < 8; ++nt) {
            const int col = n0 + wn * 64 + nt * 8 + (lane & 3) * 2;
            float v0 = gelu_exact(acc[mt][nt][0]);
            float v1 = gelu_exact(acc[mt][nt][1]);
            float v2 = gelu_exact(acc[mt][nt][2]);
            float v3 = gelu_exact(acc[mt][nt][3]);
            const size_t o0 = (size_t)row0 * 2048 + col;
            const size_t o1 = (size_t)(row0 + 8) * 2048 + col;
            __nv_bfloat16 h0, l0, h1, l1;
            split_bf16(v0, h0, l0); split_bf16(v1, h1, l1);
            *(__nv_bfloat162*)(outh + o0) = __halves2bfloat162(h0, h1);
            *(__nv_bfloat162*)(outl + o0) = __halves2bfloat162(l0, l1);
            split_bf16(v2, h0, l0); split_bf16(v3, h1, l1);
            *(__nv_bfloat162*)(outh + o1) = __halves2bfloat162(h0, h1);
            *(__nv_bfloat162*)(outl + o1) = __halves2bfloat162(l0, l1);
        }
    }
}

// ---------------------------------------------------------------------------
// proj GEMM + bias + residual + FUSED LN2 -> y fp32, yn hi/lo bf16
// ---------------------------------------------------------------------------
static constexpr int GEN_SMEM2 = 2 * 4 * TILE_B;    // 128 KB (2-stage)
static constexpr int GEN_SMEM3 = 3 * 4 * TILE_B;    // 192 KB (3-stage)

__global__ void __launch_bounds__(256, 1)
k_proj(const __nv_bfloat16* __restrict__ Ah, const __nv_bfloat16* __restrict__ Al,
       const __nv_bfloat16* __restrict__ Bh, const __nv_bfloat16* __restrict__ Bl,
       const float* __restrict__ bias, const float* __restrict__ add,
       const float* __restrict__ g2, const float* __restrict__ b2,
       float* __restrict__ y,
       __nv_bfloat16* __restrict__ ynh, __nv_bfloat16* __restrict__ ynl) {
    extern __shared__ __align__(1024) char smem[];
    const uint32_t sb = smem_u32(smem);
    const int tid = threadIdx.x, wid = tid >> 5, lane = tid & 31;
    const int wm = wid & 3, wn = wid >> 2;
    const int mrow0 = blockIdx.y * 128;

    float acc[2][8][4];
    ACC_INIT(acc);

    gemm128_mainloop<2, 2>(sb, tid, wid, lane,
        (const char*)Ah + (size_t)mrow0 * 256,
        (const char*)Al + (size_t)mrow0 * 256,
        (const char*)Bh, (const char*)Bl, 256, acc);
    __syncthreads();    // smem reused below

    // pass 1: bias + residual, write y, accumulate row sums
    float s_loc[2][2] = {{0.f,0.f},{0.f,0.f}};
    float q_loc[2][2] = {{0.f,0.f},{0.f,0.f}};
    #pragma unroll
    for (int mt = 0; mt < 2; ++mt) {
        const int r0 = mrow0 + wm * 32 + mt * 16 + (lane >> 2);
        #pragma unroll
        for (int nt = 0; nt < 8; ++nt) {
            const int col = wn * 64 + nt * 8 + (lane & 3) * 2;
            float bb0 = __ldg(&bias[col]), bb1 = __ldg(&bias[col + 1]);
            const size_t o0 = (size_t)r0 * 128 + col;
            const size_t o1 = (size_t)(r0 + 8) * 128 + col;
            float2 a0 = *(const float2*)(add + o0);
            float2 a1 = *(const float2*)(add + o1);
            float v0 = acc[mt][nt][0] + bb0 + a0.x;
            float v1 = acc[mt][nt][1] + bb1 + a0.y;
            float v2 = acc[mt][nt][2] + bb0 + a1.x;
            float v3 = acc[mt][nt][3] + bb1 + a1.y;
            *(float2*)(y + o0) = make_float2(v0, v1);
            *(float2*)(y + o1) = make_float2(v2, v3);
            acc[mt][nt][0] = v0; acc[mt][nt][1] = v1;
            acc[mt][nt][2] = v2; acc[mt][nt][3] = v3;
            s_loc[mt][0] += v0 + v1; q_loc[mt][0] += v0 * v0 + v1 * v1;
            s_loc[mt][1] += v2 + v3; q_loc[mt][1] += v2 * v2 + v3 * v3;
        }
    }
    #pragma unroll
    for (int mt = 0; mt < 2; ++mt)
        #pragma unroll
        for (int h = 0; h < 2; ++h) {
            float s = s_loc[mt][h], q = q_loc[mt][h];
            s += __shfl_xor_sync(0xffffffffu, s, 1);
            s += __shfl_xor_sync(0xffffffffu, s, 2);
            q += __shfl_xor_sync(0xffffffffu, q, 1);
            q += __shfl_xor_sync(0xffffffffu, q, 2);
            s_loc[mt][h] = s; q_loc[mt][h] = q;
        }
    float* rsum = (float*)smem;            // [128][2]
    float* rsq  = rsum + 256;
    if ((lane & 3) == 0) {
        #pragma unroll
        for (int mt = 0; mt < 2; ++mt)
            #pragma unroll
            for (int h = 0; h < 2; ++h) {
                int rl = wm * 32 + mt * 16 + h * 8 + (lane >> 2);
                rsum[rl * 2 + wn] = s_loc[mt][h];
                rsq [rl * 2 + wn] = q_loc[mt][h];
            }
    }
    __syncthreads();

    // pass 2: LN2 normalize + split bf16 out
    #pragma unroll
    for (int mt = 0; mt < 2; ++mt) {
        const int rl0 = wm * 32 + mt * 16 + (lane >> 2);
        const int rl1 = rl0 + 8;
        float S0 = rsum[rl0 * 2] + rsum[rl0 * 2 + 1];
        float Q0 = rsq [rl0 * 2] + rsq [rl0 * 2 + 1];
        float S1 = rsum[rl1 * 2] + rsum[rl1 * 2 + 1];
        float Q1 = rsq [rl1 * 2] + rsq [rl1 * 2 + 1];
        float mu0 = S0 * (1.0f / 128.0f);
        float rs0 = rsqrtf(Q0 * (1.0f / 128.0f) - mu0 * mu0 + 1e-5f);
        float mu1 = S1 * (1.0f / 128.0f);
        float rs1 = rsqrtf(Q1 * (1.0f / 128.0f) - mu1 * mu1 + 1e-5f);
        const int r0 = mrow0 + rl0;
        #pragma unroll
        for (int nt = 0; nt < 8; ++nt) {
            const int col = wn * 64 + nt * 8 + (lane & 3) * 2;
            float g0 = __ldg(&g2[col]), g1 = __ldg(&g2[col + 1]);
            float be0 = __ldg(&b2[col]), be1 = __ldg(&b2[col + 1]);
            float n0 = (acc[mt][nt][0] - mu0) * rs0 * g0 + be0;
            float n1 = (acc[mt][nt][1] - mu0) * rs0 * g1 + be1;
            float n2 = (acc[mt][nt][2] - mu1) * rs1 * g0 + be0;
            float n3 = (acc[mt][nt][3] - mu1) * rs1 * g1 + be1;
            const size_t o0 = (size_t)r0 * 128 + col;
            const size_t o1 = (size_t)(r0 + 8) * 128 + col;
            __nv_bfloat16 h0, l0, h1, l1;
            split_bf16(n0, h0, l0); split_bf16(n1, h1, l1);
            *(__nv_bfloat162*)(ynh + o0) = __halves2bfloat162(h0, h1);
            *(__nv_bfloat162*)(ynl + o0) = __halves2bfloat162(l0, l1);
            split_bf16(n2, h0, l0); split_bf16(n3, h1, l1);
            *(__nv_bfloat162*)(ynh + o1) = __halves2bfloat162(h0, h1);
            *(__nv_bfloat162*)(ynl + o1) = __halves2bfloat162(l0, l1);
        }
    }
}

// ---------------------------------------------------------------------------
// MLP1: GEMM + bias + gelu -> h hi/lo bf16.  grid (4, 1024).
// ---------------------------------------------------------------------------
__global__ void __launch_bounds__(256, 1)
k_mlp1(const __nv_bfloat16* __restrict__ Ah, const __nv_bfloat16* __restrict__ Al,
       const __nv_bfloat16* __restrict__ Bh, const __nv_bfloat16* __restrict__ Bl,
       const float* __restrict__ bias,
       __nv_bfloat16* __restrict__ outh, __nv_bfloat16* __restrict__ outl) {
    extern __shared__ __align__(1024) char smem[];
    const uint32_t sb = smem_u32(smem);
    const int tid = threadIdx.x, wid = tid >> 5, lane = tid & 31;
    const int wm = wid & 3, wn = wid >> 2;
    const int mrow0 = blockIdx.y * 128;
    const int n0    = blockIdx.x * 128;

    float acc[2][8][4];
    ACC_INIT(acc);

    gemm128_mainloop<2, 2>(sb, tid, wid, lane,
        (const char*)Ah + (size_t)mrow0 * 256,
        (const char*)Al + (size_t)mrow0 * 256,
        (const char*)Bh + (size_t)n0 * 256,
        (const char*)Bl + (size_t)n0 * 256, 256, acc);

    #pragma unroll
    for (int mt = 0; mt < 2; ++mt) {
        const int row0 = mrow0 + wm * 32 + mt * 16 + (lane >> 2);
        #pragma unroll
        for (int nt = 0; nt < 8; ++nt) {
            const int col = n0 + wn * 64 + nt * 8 + (lane & 3) * 2;
            float bb0 = __ldg(&bias[col]), bb1 = __ldg(&bias[col + 1]);
            float v0 = gelu_exact(acc[mt][nt][0] + bb0);
            float v1 = gelu_exact(acc[mt][nt][1] + bb1);
            float v2 = gelu_exact(acc[mt][nt][2] + bb0);
            float v3 = gelu_exact(acc[mt][nt][3] + bb1);
            const size_t o0 = (size_t)row0 * 512 + col;
            const size_t o1 = (size_t)(row0 + 8) * 512 + col;
            __nv_bfloat16 h0, l0, h1, l1;
            split_bf16(v0, h0, l0); split_bf16(v1, h1, l1);
            *(__nv_bfloat162*)(outh + o0) = __halves2bfloat162(h0, h1);
            *(__nv_bfloat162*)(outl + o0) = __halves2bfloat162(l0, l1);
            split_bf16(v2, h0, l0); split_bf16(v3, h1, l1);
            *(__nv_bfloat162*)(outh + o1) = __halves2bfloat162(h0, h1);
            *(__nv_bfloat162*)(outl + o1) = __halves2bfloat162(l0, l1);
        }
    }
}

// ---------------------------------------------------------------------------
// MLP2: GEMM + bias + residual, FUSED window->NCHW transpose out. grid (1,1024)
// ---------------------------------------------------------------------------
__global__ void __launch_bounds__(256, 1)
k_mlp2(const __nv_bfloat16* __restrict__ Ah, const __nv_bfloat16* __restrict__ Al,
       const __nv_bfloat16* __restrict__ Bh, const __nv_bfloat16* __restrict__ Bl,
       const float* __restrict__ bias, const float* __restrict__ add,
       float* __restrict__ out) {
    extern __shared__ __align__(1024) char smem[];
    const uint32_t sb = smem_u32(smem);
    const int tid = threadIdx.x, wid = tid >> 5, lane = tid & 31;
    const int wm = wid & 3, wn = wid >> 2;
    const int mrow0 = blockIdx.y * 128;

    float acc[2][8][4];
    ACC_INIT(acc);

    gemm128_mainloop<8, 3>(sb, tid, wid, lane,
        (const char*)Ah + (size_t)mrow0 * 1024,
        (const char*)Al + (size_t)mrow0 * 1024,
        (const char*)Bh, (const char*)Bl, 1024, acc);
    __syncthreads();    // smem reused below

    // stage into smem [row][col], pitch 132 floats
    float* stg = (float*)smem;
    #pragma unroll
    for (int mt = 0; mt < 2; ++mt) {
        const int rl = wm * 32 + mt * 16 + (lane >> 2);
        #pragma unroll
        for (int nt = 0; nt < 8; ++nt) {
            const int col = wn * 64 + nt * 8 + (lane & 3) * 2;
            float bb0 = __ldg(&bias[col]), bb1 = __ldg(&bias[col + 1]);
            const size_t o0 = (size_t)(mrow0 + rl) * 128 + col;
            const size_t o1 = (size_t)(mrow0 + rl + 8) * 128 + col;
            float2 a0 = *(const float2*)(add + o0);
            float2 a1 = *(const float2*)(add + o1);
            stg[rl * 132 + col]           = acc[mt][nt][0] + bb0 + a0.x;
            stg[rl * 132 + col + 1]       = acc[mt][nt][1] + bb1 + a0.y;
            stg[(rl + 8) * 132 + col]     = acc[mt][nt][2] + bb0 + a1.x;
            stg[(rl + 8) * 132 + col + 1] = acc[mt][nt][3] + bb1 + a1.y;
        }
    }
    __syncthreads();

    // coalesced NCHW writeout
    const int widx0 = blockIdx.y * 8;
    const int b   = widx0 >> 10;
    const int h4  = (widx0 >> 5) & 31;
    const int w40 = widx0 & 31;
    for (int seg = wid; seg < 512; seg += 8) {
        int c = seg >> 2, hh = seg & 3;
        int row = ((lane >> 2) << 4) + (hh << 2) + (lane & 3);
        float val = stg[row * 132 + c];
        out[(((size_t)(b * 128 + c)) * 128 + h4 * 4 + hh) * 128
            + w40 * 4 + lane] = val;
    }
}

// ---------------------------------------------------------------------------
// Launch
// ---------------------------------------------------------------------------
extern "C" void kernel_launch(void* const* d_in, const int* in_sizes, int n_in,
                              void* d_out, int out_size) {
    const float* x      = (const float*)d_in[0];
    const float* gamma1 = (const float*)d_in[1];
    const float* beta1  = (const float*)d_in[2];
    const float* sed_w  = (const float*)d_in[3];
    const float* w_proj = (const float*)d_in[4];
    const float* b_proj = (const float*)d_in[5];
    const float* gamma2 = (const float*)d_in[6];
    const float* beta2  = (const float*)d_in[7];
    const float* w1     = (const float*)d_in[8];
    const float* b1     = (const float*)d_in[9];
    const float* w2     = (const float*)d_in[10];
    const float* b2     = (const float*)d_in[11];
    float* out = (float*)d_out;

    float *xt, *y;
    __nv_bfloat16 *xnh, *xnl, *gh, *gl, *ynh, *ynl, *hh, *hl;
    __nv_bfloat16 *bth, *btl, *bph, *bpl, *b1h, *b1l, *b2h, *b2l;
    cudaGetSymbolAddress((void**)&xt,  g_xt);
    cudaGetSymbolAddress((void**)&y,   g_y);
    cudaGetSymbolAddress((void**)&xnh, g_xnh);
    cudaGetSymbolAddress((void**)&xnl, g_xnl);
    cudaGetSymbolAddress((void**)&gh,  g_gh);
    cudaGetSymbolAddress((void**)&gl,  g_gl);
    cudaGetSymbolAddress((void**)&ynh, g_ynh);
    cudaGetSymbolAddress((void**)&ynl, g_ynl);
    cudaGetSymbolAddress((void**)&hh,  g_hh);
    cudaGetSymbolAddress((void**)&hl,  g_hl);
    cudaGetSymbolAddress((void**)&bth, g_bth);
    cudaGetSymbolAddress((void**)&btl, g_btl);
    cudaGetSymbolAddress((void**)&bph, g_bph);
    cudaGetSymbolAddress((void**)&bpl, g_bpl);
    cudaGetSymbolAddress((void**)&b1h, g_b1h);
    cudaGetSymbolAddress((void**)&b1l, g_b1l);
    cudaGetSymbolAddress((void**)&b2h, g_b2h);
    cudaGetSymbolAddress((void**)&b2l, g_b2l);

    cudaFuncSetAttribute(k_sed,  cudaFuncAttributeMaxDynamicSharedMemorySize, SED_SMEM);
    cudaFuncSetAttribute(k_proj, cudaFuncAttributeMaxDynamicSharedMemorySize, GEN_SMEM2);
    cudaFuncSetAttribute(k_mlp1, cudaFuncAttributeMaxDynamicSharedMemorySize, GEN_SMEM2);
    cudaFuncSetAttribute(k_mlp2, cudaFuncAttributeMaxDynamicSharedMemorySize, GEN_SMEM3);

    // weight preps
    k_prep_sed<<<2048, 128>>>(sed_w, bth, btl);
    k_prep_w<<<128, 128>>>(w_proj, 128, 128, bph, bpl);
    k_prep_w<<<512, 128>>>(w1, 128, 512, b1h, b1l);
    k_prep_w<<<128, 128>>>(w2, 512, 128, b2h, b2l);

    // 1) LN1 + transpose
    k_ln1<<<dim3(512, 8), 256>>>(x, gamma1, beta1, xt, xnh, xnl);

    // 2) SED: [8192 x 2048] @ Wbig^T, gelu
    k_sed<<<dim3(16, 64), 256, SED_SMEM>>>(xnh, xnl, bth, btl, gh, gl);

    // 3) proj + residual + fused LN2
    k_proj<<<dim3(1, 1024), 256, GEN_SMEM2>>>(
        gh, gl, bph, bpl, b_proj, xt, gamma2, beta2, y, ynh, ynl);

    // 4) MLP1: + b1, gelu
    k_mlp1<<<dim3(4, 1024), 256, GEN_SMEM2>>>(
        ynh, ynl, b1h, b1l, b1, hh, hl);

    // 5) MLP2: + b2 + y, fused NCHW writeout
    k_mlp2<<<dim3(1, 1024), 256, GEN_SMEM3>>>(
        hh, hl, b2h, b2l, b2, y, out);
}

// round 6
// speedup vs baseline: 1.3971x; 1.3224x over previous
#include <cuda_runtime.h>
#include <cuda_fp16.h>
#include <cstdint>
#include <cstddef>

// ---------------------------------------------------------------------------
// Cayley-Dickson sign table:  e_i * e_j = sign(i,j) * e_{i XOR j}
// ---------------------------------------------------------------------------
constexpr int cdsign(int i, int j, int n) {
    return (n == 1) ? 1
         : (i < n/2 && j < n/2) ? cdsign(i, j, n/2)
         : (i < n/2)            ? cdsign(j - n/2, i, n/2)
         : (j < n/2)            ? cdsign(i - n/2, j, n/2) * (j == 0 ? 1 : -1)
         : -cdsign(j - n/2, i - n/2, n/2) * ((j - n/2) == 0 ? 1 : -1);
}
struct SgnTab { signed char v[16][16]; };
constexpr SgnTab make_sgn() {
    SgnTab t{};
    for (int i = 0; i < 16; ++i)
        for (int j = 0; j < 16; ++j)
            t.v[i][j] = (signed char)cdsign(i, j, 16);
    return t;
}
__constant__ SgnTab c_SGN = make_sgn();

// ---------------------------------------------------------------------------
static constexpr int C = 128, NPIX = 8 * 128 * 128;   // 131072
static constexpr int CH = 512;

// fp32 buffers
__device__ float g_xt[NPIX * C];
__device__ float g_y [NPIX * C];

// fp16 split-A operand buffers
__device__ __align__(256) __half g_xnh[NPIX * C];
__device__ __align__(256) __half g_xnl[NPIX * C];
__device__ __align__(256) __half g_gh [NPIX * C];
__device__ __align__(256) __half g_gl [NPIX * C];
__device__ __align__(256) __half g_ynh[NPIX * C];
__device__ __align__(256) __half g_ynl[NPIX * C];
__device__ __align__(256) __half g_hh [NPIX * CH];
__device__ __align__(256) __half g_hl [NPIX * CH];
// weight (B^T, n-major rows of K) buffers — single fp16
__device__ __align__(256) __half g_bt[2048 * 2048];
__device__ __align__(256) __half g_bp[128 * 128];
__device__ __align__(256) __half g_b1[512 * 128];
__device__ __align__(256) __half g_b2[128 * 512];

// ---------------------------------------------------------------------------
// PTX helpers (sm_80-compatible: cp.async, ldmatrix, mma.sync)
// ---------------------------------------------------------------------------
__device__ __forceinline__ uint32_t smem_u32(const void* p) {
    uint32_t a;
    asm("{ .reg .u64 t; cvta.to.shared.u64 t, %1; cvt.u32.u64 %0, t; }"
        : "=r"(a) : "l"(p));
    return a;
}
__device__ __forceinline__ void cp16(uint32_t dst, const void* src) {
    asm volatile("cp.async.cg.shared.global [%0], [%1], 16;" :: "r"(dst), "l"(src));
}
#define CP_COMMIT() asm volatile("cp.async.commit_group;" ::: "memory")
template<int N>
__device__ __forceinline__ void cp_wait() {
    asm volatile("cp.async.wait_group %0;" :: "n"(N) : "memory");
}
__device__ __forceinline__ void ldsm_x4(uint32_t addr, uint32_t* r) {
    asm volatile("ldmatrix.sync.aligned.m8n8.x4.shared.b16 {%0,%1,%2,%3}, [%4];"
        : "=r"(r[0]), "=r"(r[1]), "=r"(r[2]), "=r"(r[3]) : "r"(addr));
}
__device__ __forceinline__ void mma16816(float* c, const uint32_t* a, const uint32_t* b) {
    asm volatile("mma.sync.aligned.m16n8k16.row.col.f32.f16.f16.f32 "
        "{%0,%1,%2,%3}, {%4,%5,%6,%7}, {%8,%9}, {%0,%1,%2,%3};"
        : "+f"(c[0]), "+f"(c[1]), "+f"(c[2]), "+f"(c[3])
        : "r"(a[0]), "r"(a[1]), "r"(a[2]), "r"(a[3]), "r"(b[0]), "r"(b[1]));
}
__device__ __forceinline__ uint32_t swz(uint32_t off) {
    return off ^ ((off >> 3) & 0x70);
}
__device__ __forceinline__ float gelu_exact(float v) {
    return 0.5f * v * (1.0f + erff(v * 0.7071067811865476f));
}
__device__ __forceinline__ void split_f16(float v, __half& h, __half& l) {
    h = __float2half_rn(v);
    l = __float2half_rn(v - __half2float(h));
}

// ---------------------------------------------------------------------------
// LN1 + NCHW -> window-major (writes xt fp32 and xn hi/lo fp16)
// ---------------------------------------------------------------------------
__global__ void k_ln1(const float* __restrict__ x,
                      const float* __restrict__ g1,
                      const float* __restrict__ b1,
                      float* __restrict__ xt,
                      __half* __restrict__ xnh,
                      __half* __restrict__ xnl) {
    __shared__ float sh[128][33];
    __shared__ float red[2][8][32];
    __shared__ float smean[32], srstd[32];

    const int b  = blockIdx.y;
    const int s0 = blockIdx.x * 32;
    const int tp = threadIdx.x & 31;
    const int ty = threadIdx.x >> 5;

    const float* xb = x + (size_t)b * 128 * 16384 + s0;
    float sum = 0.f, sq = 0.f;
    #pragma unroll
    for (int c0 = 0; c0 < 128; c0 += 8) {
        int c = c0 + ty;
        float v = xb[(size_t)c * 16384 + tp];
        sh[c][tp] = v;
        sum += v; sq += v * v;
    }
    red[0][ty][tp] = sum; red[1][ty][tp] = sq;
    __syncthreads();
    if (ty == 0) {
        float s = 0.f, q = 0.f;
        #pragma unroll
        for (int y = 0; y < 8; ++y) { s += red[0][y][tp]; q += red[1][y][tp]; }
        float m = s * (1.0f / 128.0f);
        smean[tp] = m;
        srstd[tp] = rsqrtf(q * (1.0f / 128.0f) - m * m + 1e-5f);
    }
    __syncthreads();

    for (int l = threadIdx.x; l < 32 * 128; l += 256) {
        int p = l >> 7, c = l & 127;
        int s = s0 + p;
        int hh = s >> 7, ww = s & 127;
        int row = ((((b * 32 + (hh >> 2)) * 32 + (ww >> 2)) << 4)
                  + ((hh & 3) << 2) + (ww & 3));
        float v = sh[c][p];
        size_t idx = (size_t)row * 128 + c;
        xt[idx] = v;
        float nv = (v - smean[p]) * srstd[p] * g1[c] + b1[c];
        __half h, lo; split_f16(nv, h, lo);
        xnh[idx] = h; xnl[idx] = lo;
    }
}

// ---------------------------------------------------------------------------
// Weight preps (single fp16)
// ---------------------------------------------------------------------------
__global__ void k_prep_sed(const float* __restrict__ sed_w,
                           __half* __restrict__ bt) {
    int n = blockIdx.x;
    int nblk = n >> 7, d = n & 127;
    for (int k = threadIdx.x; k < 2048; k += 128) {
        int i = k >> 7, c = k & 127;
        int j = i ^ nblk;
        float s = (float)c_SGN.v[i][j];
        float v = s * __ldg(&sed_w[(size_t)(j * 128 + c) * 128 + d]);
        bt[(size_t)n * 2048 + k] = __float2half_rn(v);
    }
}

__global__ void k_prep_w(const float* __restrict__ W, int K, int N,
                         __half* __restrict__ bt) {
    int n = blockIdx.x;
    for (int k = threadIdx.x; k < K; k += 128) {
        bt[(size_t)n * K + k] = __float2half_rn(__ldg(&W[(size_t)k * N + n]));
    }
}

// ---------------------------------------------------------------------------
// Shared 128x128 mainloop (8 warps, warp 32x64), STAGES-deep cp.async pipe.
// fp16 2-product: D = Ah*B + Al*B (fp32 accum).  3 tiles/stage: Ah, Al, B.
// ---------------------------------------------------------------------------
static constexpr int TILE_B = 16384;

template<int KITERS, int STAGES>
__device__ __forceinline__ void gemm128_mainloop(
        uint32_t sb, int tid, int wid, int lane,
        const char* sAh, const char* sAl, const char* sB,
        size_t pitch, float acc[2][8][4]) {
    const int wm = wid & 3, wn = wid >> 2;

    auto load_stage = [&](int stage, int kt) {
        const char* src[3] = { sAh + (size_t)kt * 128, sAl + (size_t)kt * 128,
                               sB + (size_t)kt * 128 };
        #pragma unroll
        for (int t = 0; t < 3; ++t) {
            uint32_t tb = sb + (uint32_t)(stage * 3 + t) * TILE_B;
            #pragma unroll
            for (int i = 0; i < 4; ++i) {
                int l = tid + (i << 8);
                int r = l >> 3, ch = l & 7;
                uint32_t off = (uint32_t)(r * 128 + ch * 16);
                cp16(tb + swz(off), src[t] + (size_t)r * pitch + ch * 16);
            }
        }
    };

    const int a_row = wm * 32 + (lane & 15);
    const int a_kc  = (lane >> 4);
    const int b_row = wn * 64 + (lane & 7) + ((lane >> 4) & 1) * 8;
    const int b_kc  = ((lane >> 3) & 1);

    #pragma unroll
    for (int s = 0; s < STAGES - 1 && s < KITERS; ++s) {
        load_stage(s, s);
        CP_COMMIT();
    }

    for (int it = 0; it < KITERS; ++it) {
        cp_wait<STAGES - 2>();
        __syncthreads();

        if (it + STAGES - 1 < KITERS)
            load_stage((it + STAGES - 1) % STAGES, it + STAGES - 1);
        CP_COMMIT();

        const int buf = it % STAGES;
        const uint32_t bAh = sb + (uint32_t)(buf * 3 + 0) * TILE_B;
        const uint32_t bAl = sb + (uint32_t)(buf * 3 + 1) * TILE_B;
        const uint32_t bB  = sb + (uint32_t)(buf * 3 + 2) * TILE_B;

        #pragma unroll
        for (int ks = 0; ks < 4; ++ks) {
            uint32_t ah[2][4], al[2][4], bb[4][4];
            #pragma unroll
            for (int mt = 0; mt < 2; ++mt) {
                uint32_t off = swz((uint32_t)((a_row + mt * 16) * 128
                                              + (a_kc + 2 * ks) * 16));
                ldsm_x4(bAh + off, ah[mt]);
                ldsm_x4(bAl + off, al[mt]);
            }
            #pragma unroll
            for (int nt = 0; nt < 4; ++nt) {
                uint32_t off = swz((uint32_t)((b_row + nt * 16) * 128
                                              + (b_kc + 2 * ks) * 16));
                ldsm_x4(bB + off, bb[nt]);
            }
            #pragma unroll
            for (int mt = 0; mt < 2; ++mt)
                #pragma unroll
                for (int nt = 0; nt < 8; ++nt) {
                    const uint32_t* bf = &bb[nt >> 1][(nt & 1) * 2];
                    mma16816(acc[mt][nt], ah[mt], bf);
                    mma16816(acc[mt][nt], al[mt], bf);
                }
        }
    }
}

#define ACC_INIT(acc)                                  \
    _Pragma("unroll")                                  \
    for (int mt = 0; mt < 2; ++mt)                     \
        _Pragma("unroll")                              \
        for (int nt = 0; nt < 8; ++nt)                 \
            _Pragma("unroll")                          \
            for (int q = 0; q < 4; ++q) acc[mt][nt][q] = 0.f;

static constexpr int SMEM_S2 = 2 * 3 * TILE_B;    // 96 KB
static constexpr int SMEM_S3 = 3 * 3 * TILE_B;    // 144 KB

// ---------------------------------------------------------------------------
// SED: [8192 x 2048] @ Wbig^T, K=2048 (32 iters, 3 stages), gelu -> fp16 hi/lo
// ---------------------------------------------------------------------------
__global__ void __launch_bounds__(256, 1)
k_sed(const __half* __restrict__ Ah, const __half* __restrict__ Al,
      const __half* __restrict__ B,
      __half* __restrict__ outh, __half* __restrict__ outl) {
    extern __shared__ __align__(1024) char smem[];
    const uint32_t sb = smem_u32(smem);
    const int tid = threadIdx.x, wid = tid >> 5, lane = tid & 31;
    const int wm = wid & 3, wn = wid >> 2;
    const int mrow0 = blockIdx.y * 128;
    const int n0    = blockIdx.x * 128;

    float acc[2][8][4];
    ACC_INIT(acc);

    gemm128_mainloop<32, 3>(sb, tid, wid, lane,
        (const char*)Ah + (size_t)mrow0 * 4096,
        (const char*)Al + (size_t)mrow0 * 4096,
        (const char*)B + (size_t)n0 * 4096, 4096, acc);

    #pragma unroll
    for (int mt = 0; mt < 2; ++mt) {
        const int row0 = mrow0 + wm * 32 + mt * 16 + (lane >> 2);
        #pragma unroll
        for (int nt = 0; nt < 8; ++nt) {
            const int col = n0 + wn * 64 + nt * 8 + (lane & 3) * 2;
            float v0 = gelu_exact(acc[mt][nt][0]);
            float v1 = gelu_exact(acc[mt][nt][1]);
            float v2 = gelu_exact(acc[mt][nt][2]);
            float v3 = gelu_exact(acc[mt][nt][3]);
            const size_t o0 = (size_t)row0 * 2048 + col;
            const size_t o1 = (size_t)(row0 + 8) * 2048 + col;
            __half h0, l0, h1, l1;
            split_f16(v0, h0, l0); split_f16(v1, h1, l1);
            *(__half2*)(outh + o0) = __halves2half2(h0, h1);
            *(__half2*)(outl + o0) = __halves2half2(l0, l1);
            split_f16(v2, h0, l0); split_f16(v3, h1, l1);
            *(__half2*)(outh + o1) = __halves2half2(h0, h1);
            *(__half2*)(outl + o1) = __halves2half2(l0, l1);
        }
    }
}

// ---------------------------------------------------------------------------
// proj GEMM + bias + residual + FUSED LN2 -> y fp32, yn hi/lo fp16
// ---------------------------------------------------------------------------
__global__ void __launch_bounds__(256, 2)
k_proj(const __half* __restrict__ Ah, const __half* __restrict__ Al,
       const __half* __restrict__ B,
       const float* __restrict__ bias, const float* __restrict__ add,
       const float* __restrict__ g2, const float* __restrict__ b2,
       float* __restrict__ y,
       __half* __restrict__ ynh, __half* __restrict__ ynl) {
    extern __shared__ __align__(1024) char smem[];
    const uint32_t sb = smem_u32(smem);
    const int tid = threadIdx.x, wid = tid >> 5, lane = tid & 31;
    const int wm = wid & 3, wn = wid >> 2;
    const int mrow0 = blockIdx.y * 128;

    float acc[2][8][4];
    ACC_INIT(acc);

    gemm128_mainloop<2, 2>(sb, tid, wid, lane,
        (const char*)Ah + (size_t)mrow0 * 256,
        (const char*)Al + (size_t)mrow0 * 256,
        (const char*)B, 256, acc);
    __syncthreads();    // smem reused below

    // pass 1: bias + residual, write y, accumulate row sums
    float s_loc[2][2] = {{0.f,0.f},{0.f,0.f}};
    float q_loc[2][2] = {{0.f,0.f},{0.f,0.f}};
    #pragma unroll
    for (int mt = 0; mt < 2; ++mt) {
        const int r0 = mrow0 + wm * 32 + mt * 16 + (lane >> 2);
        #pragma unroll
        for (int nt = 0; nt < 8; ++nt) {
            const int col = wn * 64 + nt * 8 + (lane & 3) * 2;
            float bb0 = __ldg(&bias[col]), bb1 = __ldg(&bias[col + 1]);
            const size_t o0 = (size_t)r0 * 128 + col;
            const size_t o1 = (size_t)(r0 + 8) * 128 + col;
            float2 a0 = *(const float2*)(add + o0);
            float2 a1 = *(const float2*)(add + o1);
            float v0 = acc[mt][nt][0] + bb0 + a0.x;
            float v1 = acc[mt][nt][1] + bb1 + a0.y;
            float v2 = acc[mt][nt][2] + bb0 + a1.x;
            float v3 = acc[mt][nt][3] + bb1 + a1.y;
            *(float2*)(y + o0) = make_float2(v0, v1);
            *(float2*)(y + o1) = make_float2(v2, v3);
            acc[mt][nt][0] = v0; acc[mt][nt][1] = v1;
            acc[mt][nt][2] = v2; acc[mt][nt][3] = v3;
            s_loc[mt][0] += v0 + v1; q_loc[mt][0] += v0 * v0 + v1 * v1;
            s_loc[mt][1] += v2 + v3; q_loc[mt][1] += v2 * v2 + v3 * v3;
        }
    }
    #pragma unroll
    for (int mt = 0; mt < 2; ++mt)
        #pragma unroll
        for (int h = 0; h < 2; ++h) {
            float s = s_loc[mt][h], q = q_loc[mt][h];
            s += __shfl_xor_sync(0xffffffffu, s, 1);
            s += __shfl_xor_sync(0xffffffffu, s, 2);
            q += __shfl_xor_sync(0xffffffffu, q, 1);
            q += __shfl_xor_sync(0xffffffffu, q, 2);
            s_loc[mt][h] = s; q_loc[mt][h] = q;
        }
    float* rsum = (float*)smem;            // [128][2]
    float* rsq  = rsum + 256;
    if ((lane & 3) == 0) {
        #pragma unroll
        for (int mt = 0; mt < 2; ++mt)
            #pragma unroll
            for (int h = 0; h < 2; ++h) {
                int rl = wm * 32 + mt * 16 + h * 8 + (lane >> 2);
                rsum[rl * 2 + wn] = s_loc[mt][h];
                rsq [rl * 2 + wn] = q_loc[mt][h];
            }
    }
    __syncthreads();

    // pass 2: LN2 normalize + split fp16 out
    #pragma unroll
    for (int mt = 0; mt < 2; ++mt) {
        const int rl0 = wm * 32 + mt * 16 + (lane >> 2);
        const int rl1 = rl0 + 8;
        float S0 = rsum[rl0 * 2] + rsum[rl0 * 2 + 1];
        float Q0 = rsq [rl0 * 2] + rsq [rl0 * 2 + 1];
        float S1 = rsum[rl1 * 2] + rsum[rl1 * 2 + 1];
        float Q1 = rsq [rl1 * 2] + rsq [rl1 * 2 + 1];
        float mu0 = S0 * (1.0f / 128.0f);
        float rs0 = rsqrtf(Q0 * (1.0f / 128.0f) - mu0 * mu0 + 1e-5f);
        float mu1 = S1 * (1.0f / 128.0f);
        float rs1 = rsqrtf(Q1 * (1.0f / 128.0f) - mu1 * mu1 + 1e-5f);
        const int r0 = mrow0 + rl0;
        #pragma unroll
        for (int nt = 0; nt < 8; ++nt) {
            const int col = wn * 64 + nt * 8 + (lane & 3) * 2;
            float g0 = __ldg(&g2[col]), g1 = __ldg(&g2[col + 1]);
            float be0 = __ldg(&b2[col]), be1 = __ldg(&b2[col + 1]);
            float n0 = (acc[mt][nt][0] - mu0) * rs0 * g0 + be0;
            float n1 = (acc[mt][nt][1] - mu0) * rs0 * g1 + be1;
            float n2 = (acc[mt][nt][2] - mu1) * rs1 * g0 + be0;
            float n3 = (acc[mt][nt][3] - mu1) * rs1 * g1 + be1;
            const size_t o0 = (size_t)r0 * 128 + col;
            const size_t o1 = (size_t)(r0 + 8) * 128 + col;
            __half h0, l0, h1, l1;
            split_f16(n0, h0, l0); split_f16(n1, h1, l1);
            *(__half2*)(ynh + o0) = __halves2half2(h0, h1);
            *(__half2*)(ynl + o0) = __halves2half2(l0, l1);
            split_f16(n2, h0, l0); split_f16(n3, h1, l1);
            *(__half2*)(ynh + o1) = __halves2half2(h0, h1);
            *(__half2*)(ynl + o1) = __halves2half2(l0, l1);
        }
    }
}

// ---------------------------------------------------------------------------
// MLP1: GEMM + bias + gelu -> h hi/lo fp16.  grid (4, 1024).
// ---------------------------------------------------------------------------
__global__ void __launch_bounds__(256, 2)
k_mlp1(const __half* __restrict__ Ah, const __half* __restrict__ Al,
       const __half* __restrict__ B,
       const float* __restrict__ bias,
       __half* __restrict__ outh, __half* __restrict__ outl) {
    extern __shared__ __align__(1024) char smem[];
    const uint32_t sb = smem_u32(smem);
    const int tid = threadIdx.x, wid = tid >> 5, lane = tid & 31;
    const int wm = wid & 3, wn = wid >> 2;
    const int mrow0 = blockIdx.y * 128;
    const int n0    = blockIdx.x * 128;

    float acc[2][8][4];
    ACC_INIT(acc);

    gemm128_mainloop<2, 2>(sb, tid, wid, lane,
        (const char*)Ah + (size_t)mrow0 * 256,
        (const char*)Al + (size_t)mrow0 * 256,
        (const char*)B + (size_t)n0 * 256, 256, acc);

    #pragma unroll
    for (int mt = 0; mt < 2; ++mt) {
        const int row0 = mrow0 + wm * 32 + mt * 16 + (lane >> 2);
        #pragma unroll
        for (int nt = 0; nt < 8; ++nt) {
            const int col = n0 + wn * 64 + nt * 8 + (lane & 3) * 2;
            float bb0 = __ldg(&bias[col]), bb1 = __ldg(&bias[col + 1]);
            float v0 = gelu_exact(acc[mt][nt][0] + bb0);
            float v1 = gelu_exact(acc[mt][nt][1] + bb1);
            float v2 = gelu_exact(acc[mt][nt][2] + bb0);
            float v3 = gelu_exact(acc[mt][nt][3] + bb1);
            const size_t o0 = (size_t)row0 * 512 + col;
            const size_t o1 = (size_t)(row0 + 8) * 512 + col;
            __half h0, l0, h1, l1;
            split_f16(v0, h0, l0); split_f16(v1, h1, l1);
            *(__half2*)(outh + o0) = __halves2half2(h0, h1);
            *(__half2*)(outl + o0) = __halves2half2(l0, l1);
            split_f16(v2, h0, l0); split_f16(v3, h1, l1);
            *(__half2*)(outh + o1) = __halves2half2(h0, h1);
            *(__half2*)(outl + o1) = __halves2half2(l0, l1);
        }
    }
}

// ---------------------------------------------------------------------------
// MLP2: GEMM + bias + residual, FUSED window->NCHW transpose out. grid (1,1024)
// ---------------------------------------------------------------------------
__global__ void __launch_bounds__(256, 1)
k_mlp2(const __half* __restrict__ Ah, const __half* __restrict__ Al,
       const __half* __restrict__ B,
       const float* __restrict__ bias, const float* __restrict__ add,
       float* __restrict__ out) {
    extern __shared__ __align__(1024) char smem[];
    const uint32_t sb = smem_u32(smem);
    const int tid = threadIdx.x, wid = tid >> 5, lane = tid & 31;
    const int wm = wid & 3, wn = wid >> 2;
    const int mrow0 = blockIdx.y * 128;

    float acc[2][8][4];
    ACC_INIT(acc);

    gemm128_mainloop<8, 3>(sb, tid, wid, lane,
        (const char*)Ah + (size_t)mrow0 * 1024,
        (const char*)Al + (size_t)mrow0 * 1024,
        (const char*)B, 1024, acc);
    __syncthreads();    // smem reused below

    // stage into smem [row][col], pitch 132 floats
    float* stg = (float*)smem;
    #pragma unroll
    for (int mt = 0; mt < 2; ++mt) {
        const int rl = wm * 32 + mt * 16 + (lane >> 2);
        #pragma unroll
        for (int nt = 0; nt < 8; ++nt) {
            const int col = wn * 64 + nt * 8 + (lane & 3) * 2;
            float bb0 = __ldg(&bias[col]), bb1 = __ldg(&bias[col + 1]);
            const size_t o0 = (size_t)(mrow0 + rl) * 128 + col;
            const size_t o1 = (size_t)(mrow0 + rl + 8) * 128 + col;
            float2 a0 = *(const float2*)(add + o0);
            float2 a1 = *(const float2*)(add + o1);
            stg[rl * 132 + col]           = acc[mt][nt][0] + bb0 + a0.x;
            stg[rl * 132 + col + 1]       = acc[mt][nt][1] + bb1 + a0.y;
            stg[(rl + 8) * 132 + col]     = acc[mt][nt][2] + bb0 + a1.x;
            stg[(rl + 8) * 132 + col + 1] = acc[mt][nt][3] + bb1 + a1.y;
        }
    }
    __syncthreads();

    // coalesced NCHW writeout
    const int widx0 = blockIdx.y * 8;
    const int b   = widx0 >> 10;
    const int h4  = (widx0 >> 5) & 31;
    const int w40 = widx0 & 31;
    for (int seg = wid; seg < 512; seg += 8) {
        int c = seg >> 2, hh = seg & 3;
        int row = ((lane >> 2) << 4) + (hh << 2) + (lane & 3);
        float val = stg[row * 132 + c];
        out[(((size_t)(b * 128 + c)) * 128 + h4 * 4 + hh) * 128
            + w40 * 4 + lane] = val;
    }
}

// ---------------------------------------------------------------------------
// Launch
// ---------------------------------------------------------------------------
extern "C" void kernel_launch(void* const* d_in, const int* in_sizes, int n_in,
                              void* d_out, int out_size) {
    const float* x      = (const float*)d_in[0];
    const float* gamma1 = (const float*)d_in[1];
    const float* beta1  = (const float*)d_in[2];
    const float* sed_w  = (const float*)d_in[3];
    const float* w_proj = (const float*)d_in[4];
    const float* b_proj = (const float*)d_in[5];
    const float* gamma2 = (const float*)d_in[6];
    const float* beta2  = (const float*)d_in[7];
    const float* w1     = (const float*)d_in[8];
    const float* b1     = (const float*)d_in[9];
    const float* w2     = (const float*)d_in[10];
    const float* b2     = (const float*)d_in[11];
    float* out = (float*)d_out;

    float *xt, *y;
    __half *xnh, *xnl, *gh, *gl, *ynh, *ynl, *hh, *hl;
    __half *bt, *bp, *bw1, *bw2;
    cudaGetSymbolAddress((void**)&xt,  g_xt);
    cudaGetSymbolAddress((void**)&y,   g_y);
    cudaGetSymbolAddress((void**)&xnh, g_xnh);
    cudaGetSymbolAddress((void**)&xnl, g_xnl);
    cudaGetSymbolAddress((void**)&gh,  g_gh);
    cudaGetSymbolAddress((void**)&gl,  g_gl);
    cudaGetSymbolAddress((void**)&ynh, g_ynh);
    cudaGetSymbolAddress((void**)&ynl, g_ynl);
    cudaGetSymbolAddress((void**)&hh,  g_hh);
    cudaGetSymbolAddress((void**)&hl,  g_hl);
    cudaGetSymbolAddress((void**)&bt,  g_bt);
    cudaGetSymbolAddress((void**)&bp,  g_bp);
    cudaGetSymbolAddress((void**)&bw1, g_b1);
    cudaGetSymbolAddress((void**)&bw2, g_b2);

    cudaFuncSetAttribute(k_sed,  cudaFuncAttributeMaxDynamicSharedMemorySize, SMEM_S3);
    cudaFuncSetAttribute(k_proj, cudaFuncAttributeMaxDynamicSharedMemorySize, SMEM_S2);
    cudaFuncSetAttribute(k_mlp1, cudaFuncAttributeMaxDynamicSharedMemorySize, SMEM_S2);
    cudaFuncSetAttribute(k_mlp2, cudaFuncAttributeMaxDynamicSharedMemorySize, SMEM_S3);

    // weight preps
    k_prep_sed<<<2048, 128>>>(sed_w, bt);
    k_prep_w<<<128, 128>>>(w_proj, 128, 128, bp);
    k_prep_w<<<512, 128>>>(w1, 128, 512, bw1);
    k_prep_w<<<128, 128>>>(w2, 512, 128, bw2);

    // 1) LN1 + transpose
    k_ln1<<<dim3(512, 8), 256>>>(x, gamma1, beta1, xt, xnh, xnl);

    // 2) SED: [8192 x 2048] @ Wbig^T, gelu
    k_sed<<<dim3(16, 64), 256, SMEM_S3>>>(xnh, xnl, bt, gh, gl);

    // 3) proj + residual + fused LN2
    k_proj<<<dim3(1, 1024), 256, SMEM_S2>>>(
        gh, gl, bp, b_proj, xt, gamma2, beta2, y, ynh, ynl);

    // 4) MLP1: + b1, gelu
    k_mlp1<<<dim3(4, 1024), 256, SMEM_S2>>>(
        ynh, ynl, bw1, b1, hh, hl);

    // 5) MLP2: + b2 + y, fused NCHW writeout
    k_mlp2<<<dim3(1, 1024), 256, SMEM_S3>>>(
        hh, hl, bw2, b2, y, out);
}

// round 7
// speedup vs baseline: 2.3581x; 1.6879x over previous
#include <cuda_runtime.h>
#include <cuda_fp16.h>
#include <cstdint>
#include <cstddef>

// ---------------------------------------------------------------------------
// Cayley-Dickson sign table:  e_i * e_j = sign(i,j) * e_{i XOR j}
// ---------------------------------------------------------------------------
constexpr int cdsign(int i, int j, int n) {
    return (n == 1) ? 1
         : (i < n/2 && j < n/2) ? cdsign(i, j, n/2)
         : (i < n/2)            ? cdsign(j - n/2, i, n/2)
         : (j < n/2)            ? cdsign(i - n/2, j, n/2) * (j == 0 ? 1 : -1)
         : -cdsign(j - n/2, i - n/2, n/2) * ((j - n/2) == 0 ? 1 : -1);
}
struct SgnTab { signed char v[16][16]; };
constexpr SgnTab make_sgn() {
    SgnTab t{};
    for (int i = 0; i < 16; ++i)
        for (int j = 0; j < 16; ++j)
            t.v[i][j] = (signed char)cdsign(i, j, 16);
    return t;
}
__constant__ SgnTab c_SGN = make_sgn();

// ---------------------------------------------------------------------------
static constexpr int C = 128, NPIX = 8 * 128 * 128;   // 131072
static constexpr int CH = 512;

// fp32 buffers
__device__ float g_xt[NPIX * C];
__device__ float g_y [NPIX * C];

// fp16 operand buffers (single precision level — error model calibrated)
__device__ __align__(256) __half g_xn[NPIX * C];
__device__ __align__(256) __half g_g [NPIX * C];
__device__ __align__(256) __half g_yn[NPIX * C];
__device__ __align__(256) __half g_h [NPIX * CH];
// weight (B^T, n-major rows of K) buffers
__device__ __align__(256) __half g_bt[2048 * 2048];
__device__ __align__(256) __half g_bp[128 * 128];
__device__ __align__(256) __half g_b1[512 * 128];
__device__ __align__(256) __half g_b2[128 * 512];

// ---------------------------------------------------------------------------
// PTX helpers (sm_80-compatible: cp.async, ldmatrix, mma.sync)
// ---------------------------------------------------------------------------
__device__ __forceinline__ uint32_t smem_u32(const void* p) {
    uint32_t a;
    asm("{ .reg .u64 t; cvta.to.shared.u64 t, %1; cvt.u32.u64 %0, t; }"
        : "=r"(a) : "l"(p));
    return a;
}
__device__ __forceinline__ void cp16(uint32_t dst, const void* src) {
    asm volatile("cp.async.cg.shared.global [%0], [%1], 16;" :: "r"(dst), "l"(src));
}
#define CP_COMMIT() asm volatile("cp.async.commit_group;" ::: "memory")
template<int N>
__device__ __forceinline__ void cp_wait() {
    asm volatile("cp.async.wait_group %0;" :: "n"(N) : "memory");
}
__device__ __forceinline__ void ldsm_x4(uint32_t addr, uint32_t* r) {
    asm volatile("ldmatrix.sync.aligned.m8n8.x4.shared.b16 {%0,%1,%2,%3}, [%4];"
        : "=r"(r[0]), "=r"(r[1]), "=r"(r[2]), "=r"(r[3]) : "r"(addr));
}
__device__ __forceinline__ void mma16816(float* c, const uint32_t* a, const uint32_t* b) {
    asm volatile("mma.sync.aligned.m16n8k16.row.col.f32.f16.f16.f32 "
        "{%0,%1,%2,%3}, {%4,%5,%6,%7}, {%8,%9}, {%0,%1,%2,%3};"
        : "+f"(c[0]), "+f"(c[1]), "+f"(c[2]), "+f"(c[3])
        : "r"(a[0]), "r"(a[1]), "r"(a[2]), "r"(a[3]), "r"(b[0]), "r"(b[1]));
}
__device__ __forceinline__ uint32_t swz(uint32_t off) {
    return off ^ ((off >> 3) & 0x70);
}
__device__ __forceinline__ float gelu_exact(float v) {
    return 0.5f * v * (1.0f + erff(v * 0.7071067811865476f));
}

// ---------------------------------------------------------------------------
// LN1 + NCHW -> window-major (writes xt fp32 and xn fp16)
// ---------------------------------------------------------------------------
__global__ void k_ln1(const float* __restrict__ x,
                      const float* __restrict__ g1,
                      const float* __restrict__ b1,
                      float* __restrict__ xt,
                      __half* __restrict__ xn) {
    __shared__ float sh[128][33];
    __shared__ float red[2][8][32];
    __shared__ float smean[32], srstd[32];

    const int b  = blockIdx.y;
    const int s0 = blockIdx.x * 32;
    const int tp = threadIdx.x & 31;
    const int ty = threadIdx.x >> 5;

    const float* xb = x + (size_t)b * 128 * 16384 + s0;
    float sum = 0.f, sq = 0.f;
    #pragma unroll
    for (int c0 = 0; c0 < 128; c0 += 8) {
        int c = c0 + ty;
        float v = xb[(size_t)c * 16384 + tp];
        sh[c][tp] = v;
        sum += v; sq += v * v;
    }
    red[0][ty][tp] = sum; red[1][ty][tp] = sq;
    __syncthreads();
    if (ty == 0) {
        float s = 0.f, q = 0.f;
        #pragma unroll
        for (int y = 0; y < 8; ++y) { s += red[0][y][tp]; q += red[1][y][tp]; }
        float m = s * (1.0f / 128.0f);
        smean[tp] = m;
        srstd[tp] = rsqrtf(q * (1.0f / 128.0f) - m * m + 1e-5f);
    }
    __syncthreads();

    for (int l = threadIdx.x; l < 32 * 128; l += 256) {
        int p = l >> 7, c = l & 127;
        int s = s0 + p;
        int hh = s >> 7, ww = s & 127;
        int row = ((((b * 32 + (hh >> 2)) * 32 + (ww >> 2)) << 4)
                  + ((hh & 3) << 2) + (ww & 3));
        float v = sh[c][p];
        size_t idx = (size_t)row * 128 + c;
        xt[idx] = v;
        xn[idx] = __float2half_rn((v - smean[p]) * srstd[p] * g1[c] + b1[c]);
    }
}

// ---------------------------------------------------------------------------
// Weight preps
// ---------------------------------------------------------------------------
__global__ void k_prep_sed(const float* __restrict__ sed_w,
                           __half* __restrict__ bt) {
    int n = blockIdx.x;
    int nblk = n >> 7, d = n & 127;
    for (int k = threadIdx.x; k < 2048; k += 128) {
        int i = k >> 7, c = k & 127;
        int j = i ^ nblk;
        float s = (float)c_SGN.v[i][j];
        float v = s * __ldg(&sed_w[(size_t)(j * 128 + c) * 128 + d]);
        bt[(size_t)n * 2048 + k] = __float2half_rn(v);
    }
}

__global__ void k_prep_w(const float* __restrict__ W, int K, int N,
                         __half* __restrict__ bt) {
    int n = blockIdx.x;
    for (int k = threadIdx.x; k < K; k += 128) {
        bt[(size_t)n * K + k] = __float2half_rn(__ldg(&W[(size_t)k * N + n]));
    }
}

// ---------------------------------------------------------------------------
// Shared 128x128 mainloop (8 warps, warp 32x64), STAGES-deep cp.async pipe.
// Pure fp16 single product: D = A*B (fp32 accum).  2 tiles/stage: A, B.
// ---------------------------------------------------------------------------
static constexpr int TILE_B = 16384;

template<int KITERS, int STAGES>
__device__ __forceinline__ void gemm128_mainloop(
        uint32_t sb, int tid, int wid, int lane,
        const char* sA, const char* sB,
        size_t pitch, float acc[2][8][4]) {
    const int wm = wid & 3, wn = wid >> 2;

    auto load_stage = [&](int stage, int kt) {
        const char* src[2] = { sA + (size_t)kt * 128, sB + (size_t)kt * 128 };
        #pragma unroll
        for (int t = 0; t < 2; ++t) {
            uint32_t tb = sb + (uint32_t)(stage * 2 + t) * TILE_B;
            #pragma unroll
            for (int i = 0; i < 4; ++i) {
                int l = tid + (i << 8);
                int r = l >> 3, ch = l & 7;
                uint32_t off = (uint32_t)(r * 128 + ch * 16);
                cp16(tb + swz(off), src[t] + (size_t)r * pitch + ch * 16);
            }
        }
    };

    const int a_row = wm * 32 + (lane & 15);
    const int a_kc  = (lane >> 4);
    const int b_row = wn * 64 + (lane & 7) + ((lane >> 4) & 1) * 8;
    const int b_kc  = ((lane >> 3) & 1);

    #pragma unroll
    for (int s = 0; s < STAGES - 1 && s < KITERS; ++s) {
        load_stage(s, s);
        CP_COMMIT();
    }

    for (int it = 0; it < KITERS; ++it) {
        cp_wait<STAGES - 2>();
        __syncthreads();

        if (it + STAGES - 1 < KITERS)
            load_stage((it + STAGES - 1) % STAGES, it + STAGES - 1);
        CP_COMMIT();

        const int buf = it % STAGES;
        const uint32_t bA = sb + (uint32_t)(buf * 2 + 0) * TILE_B;
        const uint32_t bB = sb + (uint32_t)(buf * 2 + 1) * TILE_B;

        #pragma unroll
        for (int ks = 0; ks < 4; ++ks) {
            uint32_t ar[2][4], bb[4][4];
            #pragma unroll
            for (int mt = 0; mt < 2; ++mt) {
                uint32_t off = swz((uint32_t)((a_row + mt * 16) * 128
                                              + (a_kc + 2 * ks) * 16));
                ldsm_x4(bA + off, ar[mt]);
            }
            #pragma unroll
            for (int nt = 0; nt < 4; ++nt) {
                uint32_t off = swz((uint32_t)((b_row + nt * 16) * 128
                                              + (b_kc + 2 * ks) * 16));
                ldsm_x4(bB + off, bb[nt]);
            }
            #pragma unroll
            for (int mt = 0; mt < 2; ++mt)
                #pragma unroll
                for (int nt = 0; nt < 8; ++nt)
                    mma16816(acc[mt][nt], ar[mt], &bb[nt >> 1][(nt & 1) * 2]);
        }
    }
}

#define ACC_INIT(acc)                                  \
    _Pragma("unroll")                                  \
    for (int mt = 0; mt < 2; ++mt)                     \
        _Pragma("unroll")                              \
        for (int nt = 0; nt < 8; ++nt)                 \
            _Pragma("unroll")                          \
            for (int q = 0; q < 4; ++q) acc[mt][nt][q] = 0.f;

static constexpr int SMEM_S2 = 2 * 2 * TILE_B;    // 64 KB
static constexpr int SMEM_S3 = 3 * 2 * TILE_B;    // 96 KB

// ---------------------------------------------------------------------------
// SED: [8192 x 2048] @ Wbig^T, K=2048 (32 iters, 3 stages), gelu -> fp16
// ---------------------------------------------------------------------------
__global__ void __launch_bounds__(256, 2)
k_sed(const __half* __restrict__ A, const __half* __restrict__ B,
      __half* __restrict__ outg) {
    extern __shared__ __align__(1024) char smem[];
    const uint32_t sb = smem_u32(smem);
    const int tid = threadIdx.x, wid = tid >> 5, lane = tid & 31;
    const int wm = wid & 3, wn = wid >> 2;
    const int mrow0 = blockIdx.y * 128;
    const int n0    = blockIdx.x * 128;

    float acc[2][8][4];
    ACC_INIT(acc);

    gemm128_mainloop<32, 3>(sb, tid, wid, lane,
        (const char*)A + (size_t)mrow0 * 4096,
        (const char*)B + (size_t)n0 * 4096, 4096, acc);

    #pragma unroll
    for (int mt = 0; mt < 2; ++mt) {
        const int row0 = mrow0 + wm * 32 + mt * 16 + (lane >> 2);
        #pragma unroll
        for (int nt = 0; nt < 8; ++nt) {
            const int col = n0 + wn * 64 + nt * 8 + (lane & 3) * 2;
            float v0 = gelu_exact(acc[mt][nt][0]);
            float v1 = gelu_exact(acc[mt][nt][1]);
            float v2 = gelu_exact(acc[mt][nt][2]);
            float v3 = gelu_exact(acc[mt][nt][3]);
            const size_t o0 = (size_t)row0 * 2048 + col;
            const size_t o1 = (size_t)(row0 + 8) * 2048 + col;
            *(__half2*)(outg + o0) =
                __halves2half2(__float2half_rn(v0), __float2half_rn(v1));
            *(__half2*)(outg + o1) =
                __halves2half2(__float2half_rn(v2), __float2half_rn(v3));
        }
    }
}

// ---------------------------------------------------------------------------
// proj GEMM + bias + residual + FUSED LN2 -> y fp32, yn fp16
// ---------------------------------------------------------------------------
__global__ void __launch_bounds__(256, 2)
k_proj(const __half* __restrict__ A, const __half* __restrict__ B,
       const float* __restrict__ bias, const float* __restrict__ add,
       const float* __restrict__ g2, const float* __restrict__ b2,
       float* __restrict__ y, __half* __restrict__ yn) {
    extern __shared__ __align__(1024) char smem[];
    const uint32_t sb = smem_u32(smem);
    const int tid = threadIdx.x, wid = tid >> 5, lane = tid & 31;
    const int wm = wid & 3, wn = wid >> 2;
    const int mrow0 = blockIdx.y * 128;

    float acc[2][8][4];
    ACC_INIT(acc);

    gemm128_mainloop<2, 2>(sb, tid, wid, lane,
        (const char*)A + (size_t)mrow0 * 256,
        (const char*)B, 256, acc);
    __syncthreads();    // smem reused below

    // pass 1: bias + residual, write y, accumulate row sums
    float s_loc[2][2] = {{0.f,0.f},{0.f,0.f}};
    float q_loc[2][2] = {{0.f,0.f},{0.f,0.f}};
    #pragma unroll
    for (int mt = 0; mt < 2; ++mt) {
        const int r0 = mrow0 + wm * 32 + mt * 16 + (lane >> 2);
        #pragma unroll
        for (int nt = 0; nt < 8; ++nt) {
            const int col = wn * 64 + nt * 8 + (lane & 3) * 2;
            float bb0 = __ldg(&bias[col]), bb1 = __ldg(&bias[col + 1]);
            const size_t o0 = (size_t)r0 * 128 + col;
            const size_t o1 = (size_t)(r0 + 8) * 128 + col;
            float2 a0 = *(const float2*)(add + o0);
            float2 a1 = *(const float2*)(add + o1);
            float v0 = acc[mt][nt][0] + bb0 + a0.x;
            float v1 = acc[mt][nt][1] + bb1 + a0.y;
            float v2 = acc[mt][nt][2] + bb0 + a1.x;
            float v3 = acc[mt][nt][3] + bb1 + a1.y;
            *(float2*)(y + o0) = make_float2(v0, v1);
            *(float2*)(y + o1) = make_float2(v2, v3);
            acc[mt][nt][0] = v0; acc[mt][nt][1] = v1;
            acc[mt][nt][2] = v2; acc[mt][nt][3] = v3;
            s_loc[mt][0] += v0 + v1; q_loc[mt][0] += v0 * v0 + v1 * v1;
            s_loc[mt][1] += v2 + v3; q_loc[mt][1] += v2 * v2 + v3 * v3;
        }
    }
    #pragma unroll
    for (int mt = 0; mt < 2; ++mt)
        #pragma unroll
        for (int h = 0; h < 2; ++h) {
            float s = s_loc[mt][h], q = q_loc[mt][h];
            s += __shfl_xor_sync(0xffffffffu, s, 1);
            s += __shfl_xor_sync(0xffffffffu, s, 2);
            q += __shfl_xor_sync(0xffffffffu, q, 1);
            q += __shfl_xor_sync(0xffffffffu, q, 2);
            s_loc[mt][h] = s; q_loc[mt][h] = q;
        }
    float* rsum = (float*)smem;            // [128][2]
    float* rsq  = rsum + 256;
    if ((lane & 3) == 0) {
        #pragma unroll
        for (int mt = 0; mt < 2; ++mt)
            #pragma unroll
            for (int h = 0; h < 2; ++h) {
                int rl = wm * 32 + mt * 16 + h * 8 + (lane >> 2);
                rsum[rl * 2 + wn] = s_loc[mt][h];
                rsq [rl * 2 + wn] = q_loc[mt][h];
            }
    }
    __syncthreads();

    // pass 2: LN2 normalize -> fp16 out
    #pragma unroll
    for (int mt = 0; mt < 2; ++mt) {
        const int rl0 = wm * 32 + mt * 16 + (lane >> 2);
        const int rl1 = rl0 + 8;
        float S0 = rsum[rl0 * 2] + rsum[rl0 * 2 + 1];
        float Q0 = rsq [rl0 * 2] + rsq [rl0 * 2 + 1];
        float S1 = rsum[rl1 * 2] + rsum[rl1 * 2 + 1];
        float Q1 = rsq [rl1 * 2] + rsq [rl1 * 2 + 1];
        float mu0 = S0 * (1.0f / 128.0f);
        float rs0 = rsqrtf(Q0 * (1.0f / 128.0f) - mu0 * mu0 + 1e-5f);
        float mu1 = S1 * (1.0f / 128.0f);
        float rs1 = rsqrtf(Q1 * (1.0f / 128.0f) - mu1 * mu1 + 1e-5f);
        const int r0 = mrow0 + rl0;
        #pragma unroll
        for (int nt = 0; nt < 8; ++nt) {
            const int col = wn * 64 + nt * 8 + (lane & 3) * 2;
            float g0 = __ldg(&g2[col]), g1 = __ldg(&g2[col + 1]);
            float be0 = __ldg(&b2[col]), be1 = __ldg(&b2[col + 1]);
            float n0 = (acc[mt][nt][0] - mu0) * rs0 * g0 + be0;
            float n1 = (acc[mt][nt][1] - mu0) * rs0 * g1 + be1;
            float n2 = (acc[mt][nt][2] - mu1) * rs1 * g0 + be0;
            float n3 = (acc[mt][nt][3] - mu1) * rs1 * g1 + be1;
            const size_t o0 = (size_t)r0 * 128 + col;
            const size_t o1 = (size_t)(r0 + 8) * 128 + col;
            *(__half2*)(yn + o0) =
                __halves2half2(__float2half_rn(n0), __float2half_rn(n1));
            *(__half2*)(yn + o1) =
                __halves2half2(__float2half_rn(n2), __float2half_rn(n3));
        }
    }
}

// ---------------------------------------------------------------------------
// MLP1: GEMM + bias + gelu -> h fp16.  grid (4, 1024).
// ---------------------------------------------------------------------------
__global__ void __launch_bounds__(256, 2)
k_mlp1(const __half* __restrict__ A, const __half* __restrict__ B,
       const float* __restrict__ bias, __half* __restrict__ outh) {
    extern __shared__ __align__(1024) char smem[];
    const uint32_t sb = smem_u32(smem);
    const int tid = threadIdx.x, wid = tid >> 5, lane = tid & 31;
    const int wm = wid & 3, wn = wid >> 2;
    const int mrow0 = blockIdx.y * 128;
    const int n0    = blockIdx.x * 128;

    float acc[2][8][4];
    ACC_INIT(acc);

    gemm128_mainloop<2, 2>(sb, tid, wid, lane,
        (const char*)A + (size_t)mrow0 * 256,
        (const char*)B + (size_t)n0 * 256, 256, acc);

    #pragma unroll
    for (int mt = 0; mt < 2; ++mt) {
        const int row0 = mrow0 + wm * 32 + mt * 16 + (lane >> 2);
        #pragma unroll
        for (int nt = 0; nt < 8; ++nt) {
            const int col = n0 + wn * 64 + nt * 8 + (lane & 3) * 2;
            float bb0 = __ldg(&bias[col]), bb1 = __ldg(&bias[col + 1]);
            float v0 = gelu_exact(acc[mt][nt][0] + bb0);
            float v1 = gelu_exact(acc[mt][nt][1] + bb1);
            float v2 = gelu_exact(acc[mt][nt][2] + bb0);
            float v3 = gelu_exact(acc[mt][nt][3] + bb1);
            const size_t o0 = (size_t)row0 * 512 + col;
            const size_t o1 = (size_t)(row0 + 8) * 512 + col;
            *(__half2*)(outh + o0) =
                __halves2half2(__float2half_rn(v0), __float2half_rn(v1));
            *(__half2*)(outh + o1) =
                __halves2half2(__float2half_rn(v2), __float2half_rn(v3));
        }
    }
}

// ---------------------------------------------------------------------------
// MLP2: GEMM + bias + residual, FUSED window->NCHW transpose out. grid (1,1024)
// ---------------------------------------------------------------------------
__global__ void __launch_bounds__(256, 2)
k_mlp2(const __half* __restrict__ A, const __half* __restrict__ B,
       const float* __restrict__ bias, const float* __restrict__ add,
       float* __restrict__ out) {
    extern __shared__ __align__(1024) char smem[];
    const uint32_t sb = smem_u32(smem);
    const int tid = threadIdx.x, wid = tid >> 5, lane = tid & 31;
    const int wm = wid & 3, wn = wid >> 2;
    const int mrow0 = blockIdx.y * 128;

    float acc[2][8][4];
    ACC_INIT(acc);

    gemm128_mainloop<8, 3>(sb, tid, wid, lane,
        (const char*)A + (size_t)mrow0 * 1024,
        (const char*)B, 1024, acc);
    __syncthreads();    // smem reused below

    // stage into smem [row][col], pitch 132 floats
    float* stg = (float*)smem;
    #pragma unroll
    for (int mt = 0; mt < 2; ++mt) {
        const int rl = wm * 32 + mt * 16 + (lane >> 2);
        #pragma unroll
        for (int nt = 0; nt < 8; ++nt) {
            const int col = wn * 64 + nt * 8 + (lane & 3) * 2;
            float bb0 = __ldg(&bias[col]), bb1 = __ldg(&bias[col + 1]);
            const size_t o0 = (size_t)(mrow0 + rl) * 128 + col;
            const size_t o1 = (size_t)(mrow0 + rl + 8) * 128 + col;
            float2 a0 = *(const float2*)(add + o0);
            float2 a1 = *(const float2*)(add + o1);
            stg[rl * 132 + col]           = acc[mt][nt][0] + bb0 + a0.x;
            stg[rl * 132 + col + 1]       = acc[mt][nt][1] + bb1 + a0.y;
            stg[(rl + 8) * 132 + col]     = acc[mt][nt][2] + bb0 + a1.x;
            stg[(rl + 8) * 132 + col + 1] = acc[mt][nt][3] + bb1 + a1.y;
        }
    }
    __syncthreads();

    // coalesced NCHW writeout
    const int widx0 = blockIdx.y * 8;
    const int b   = widx0 >> 10;
    const int h4  = (widx0 >> 5) & 31;
    const int w40 = widx0 & 31;
    for (int seg = wid; seg < 512; seg += 8) {
        int c = seg >> 2, hh = seg & 3;
        int row = ((lane >> 2) << 4) + (hh << 2) + (lane & 3);
        float val = stg[row * 132 + c];
        out[(((size_t)(b * 128 + c)) * 128 + h4 * 4 + hh) * 128
            + w40 * 4 + lane] = val;
    }
}

// ---------------------------------------------------------------------------
// Launch
// ---------------------------------------------------------------------------
extern "C" void kernel_launch(void* const* d_in, const int* in_sizes, int n_in,
                              void* d_out, int out_size) {
    const float* x      = (const float*)d_in[0];
    const float* gamma1 = (const float*)d_in[1];
    const float* beta1  = (const float*)d_in[2];
    const float* sed_w  = (const float*)d_in[3];
    const float* w_proj = (const float*)d_in[4];
    const float* b_proj = (const float*)d_in[5];
    const float* gamma2 = (const float*)d_in[6];
    const float* beta2  = (const float*)d_in[7];
    const float* w1     = (const float*)d_in[8];
    const float* b1     = (const float*)d_in[9];
    const float* w2     = (const float*)d_in[10];
    const float* b2     = (const float*)d_in[11];
    float* out = (float*)d_out;

    float *xt, *y;
    __half *xn, *g, *yn, *h;
    __half *bt, *bp, *bw1, *bw2;
    cudaGetSymbolAddress((void**)&xt, g_xt);
    cudaGetSymbolAddress((void**)&y,  g_y);
    cudaGetSymbolAddress((void**)&xn, g_xn);
    cudaGetSymbolAddress((void**)&g,  g_g);
    cudaGetSymbolAddress((void**)&yn, g_yn);
    cudaGetSymbolAddress((void**)&h,  g_h);
    cudaGetSymbolAddress((void**)&bt, g_bt);
    cudaGetSymbolAddress((void**)&bp, g_bp);
    cudaGetSymbolAddress((void**)&bw1, g_b1);
    cudaGetSymbolAddress((void**)&bw2, g_b2);

    cudaFuncSetAttribute(k_sed,  cudaFuncAttributeMaxDynamicSharedMemorySize, SMEM_S3);
    cudaFuncSetAttribute(k_proj, cudaFuncAttributeMaxDynamicSharedMemorySize, SMEM_S2);
    cudaFuncSetAttribute(k_mlp1, cudaFuncAttributeMaxDynamicSharedMemorySize, SMEM_S2);
    cudaFuncSetAttribute(k_mlp2, cudaFuncAttributeMaxDynamicSharedMemorySize, SMEM_S3);

    // weight preps
    k_prep_sed<<<2048, 128>>>(sed_w, bt);
    k_prep_w<<<128, 128>>>(w_proj, 128, 128, bp);
    k_prep_w<<<512, 128>>>(w1, 128, 512, bw1);
    k_prep_w<<<128, 128>>>(w2, 512, 128, bw2);

    // 1) LN1 + transpose
    k_ln1<<<dim3(512, 8), 256>>>(x, gamma1, beta1, xt, xn);

    // 2) SED: [8192 x 2048] @ Wbig^T, gelu
    k_sed<<<dim3(16, 64), 256, SMEM_S3>>>(xn, bt, g);

    // 3) proj + residual + fused LN2
    k_proj<<<dim3(1, 1024), 256, SMEM_S2>>>(
        g, bp, b_proj, xt, gamma2, beta2, y, yn);

    // 4) MLP1: + b1, gelu
    k_mlp1<<<dim3(4, 1024), 256, SMEM_S2>>>(yn, bw1, b1, h);

    // 5) MLP2: + b2 + y, fused NCHW writeout
    k_mlp2<<<dim3(1, 1024), 256, SMEM_S3>>>(h, bw2, b2, y, out);
}

// round 8
// speedup vs baseline: 2.4894x; 1.0557x over previous
#include <cuda_runtime.h>
#include <cuda_fp16.h>
#include <cstdint>
#include <cstddef>

// ---------------------------------------------------------------------------
// Cayley-Dickson sign table:  e_i * e_j = sign(i,j) * e_{i XOR j}
// ---------------------------------------------------------------------------
constexpr int cdsign(int i, int j, int n) {
    return (n == 1) ? 1
         : (i < n/2 && j < n/2) ? cdsign(i, j, n/2)
         : (i < n/2)            ? cdsign(j - n/2, i, n/2)
         : (j < n/2)            ? cdsign(i - n/2, j, n/2) * (j == 0 ? 1 : -1)
         : -cdsign(j - n/2, i - n/2, n/2) * ((j - n/2) == 0 ? 1 : -1);
}
struct SgnTab { signed char v[16][16]; };
constexpr SgnTab make_sgn() {
    SgnTab t{};
    for (int i = 0; i < 16; ++i)
        for (int j = 0; j < 16; ++j)
            t.v[i][j] = (signed char)cdsign(i, j, 16);
    return t;
}
__constant__ SgnTab c_SGN = make_sgn();

// ---------------------------------------------------------------------------
static constexpr int C = 128, NPIX = 8 * 128 * 128;   // 131072

// fp32 buffers
__device__ float g_xt[NPIX * C];
__device__ float g_y [NPIX * C];

// fp16 operand buffers
__device__ __align__(256) __half g_xn[NPIX * C];
__device__ __align__(256) __half g_yn[NPIX * C];
// weight (B^T, n-major rows of K) buffers
__device__ __align__(256) __half g_bt[2048 * 2048];
__device__ __align__(256) __half g_bp[128 * 128];
__device__ __align__(256) __half g_b1[512 * 128];
__device__ __align__(256) __half g_b2[128 * 512];

// ---------------------------------------------------------------------------
// PTX helpers
// ---------------------------------------------------------------------------
__device__ __forceinline__ uint32_t smem_u32(const void* p) {
    uint32_t a;
    asm("{ .reg .u64 t; cvta.to.shared.u64 t, %1; cvt.u32.u64 %0, t; }"
        : "=r"(a) : "l"(p));
    return a;
}
__device__ __forceinline__ void cp16(uint32_t dst, const void* src) {
    asm volatile("cp.async.cg.shared.global [%0], [%1], 16;" :: "r"(dst), "l"(src));
}
#define CP_COMMIT() asm volatile("cp.async.commit_group;" ::: "memory")
template<int N>
__device__ __forceinline__ void cp_wait() {
    asm volatile("cp.async.wait_group %0;" :: "n"(N) : "memory");
}
__device__ __forceinline__ void ldsm_x4(uint32_t addr, uint32_t* r) {
    asm volatile("ldmatrix.sync.aligned.m8n8.x4.shared.b16 {%0,%1,%2,%3}, [%4];"
        : "=r"(r[0]), "=r"(r[1]), "=r"(r[2]), "=r"(r[3]) : "r"(addr));
}
__device__ __forceinline__ void mma16816(float* c, const uint32_t* a, const uint32_t* b) {
    asm volatile("mma.sync.aligned.m16n8k16.row.col.f32.f16.f16.f32 "
        "{%0,%1,%2,%3}, {%4,%5,%6,%7}, {%8,%9}, {%0,%1,%2,%3};"
        : "+f"(c[0]), "+f"(c[1]), "+f"(c[2]), "+f"(c[3])
        : "r"(a[0]), "r"(a[1]), "r"(a[2]), "r"(a[3]), "r"(b[0]), "r"(b[1]));
}
__device__ __forceinline__ uint32_t swz(uint32_t off) {
    return off ^ ((off >> 3) & 0x70);
}
__device__ __forceinline__ float gelu_exact(float v) {
    return 0.5f * v * (1.0f + erff(v * 0.7071067811865476f));
}

static constexpr int TILE_B = 16384;   // one 128-row x 128-byte (K64) tile

// Load one K64 tile (128 rows x 128 B) into smem, swizzled. 256 threads.
__device__ __forceinline__ void load_tile(uint32_t dst, const char* src,
                                          size_t pitch, int tid) {
    #pragma unroll
    for (int i = 0; i < 4; ++i) {
        int l = tid + (i << 8);
        int r = l >> 3, ch = l & 7;
        uint32_t off = (uint32_t)(r * 128 + ch * 16);
        cp16(dst + swz(off), src + (size_t)r * pitch + ch * 16);
    }
}

// One K64 compute step from resident smem tiles (bA, bB).
__device__ __forceinline__ void k64_compute(uint32_t bA, uint32_t bB,
        int a_row, int a_kc, int b_row, int b_kc, float acc[2][8][4]) {
    #pragma unroll
    for (int ks = 0; ks < 4; ++ks) {
        uint32_t ar[2][4], bb[4][4];
        #pragma unroll
        for (int mt = 0; mt < 2; ++mt) {
            uint32_t off = swz((uint32_t)((a_row + mt * 16) * 128
                                          + (a_kc + 2 * ks) * 16));
            ldsm_x4(bA + off, ar[mt]);
        }
        #pragma unroll
        for (int nt = 0; nt < 4; ++nt) {
            uint32_t off = swz((uint32_t)((b_row + nt * 16) * 128
                                          + (b_kc + 2 * ks) * 16));
            ldsm_x4(bB + off, bb[nt]);
        }
        #pragma unroll
        for (int mt = 0; mt < 2; ++mt)
            #pragma unroll
            for (int nt = 0; nt < 8; ++nt)
                mma16816(acc[mt][nt], ar[mt], &bb[nt >> 1][(nt & 1) * 2]);
    }
}

#define LANE_IDX(wid, lane)                                        \
    const int wm = (wid) & 3, wn = (wid) >> 2;                     \
    const int a_row = wm * 32 + ((lane) & 15);                     \
    const int a_kc  = ((lane) >> 4);                               \
    const int b_row = wn * 64 + ((lane) & 7) + (((lane) >> 4) & 1) * 8; \
    const int b_kc  = (((lane) >> 3) & 1);

// Streamed mainloop: STAGES-deep cp.async pipe over A,B from global.
template<int KITERS, int STAGES>
__device__ __forceinline__ void gemm128_mainloop(
        uint32_t sb, int tid, int wid, int lane,
        const char* sA, const char* sB, size_t pitch, float acc[2][8][4]) {
    LANE_IDX(wid, lane);
    auto load_stage = [&](int stage, int kt) {
        load_tile(sb + (uint32_t)(stage * 2 + 0) * TILE_B, sA + (size_t)kt * 128, pitch, tid);
        load_tile(sb + (uint32_t)(stage * 2 + 1) * TILE_B, sB + (size_t)kt * 128, pitch, tid);
    };
    #pragma unroll
    for (int s = 0; s < STAGES - 1 && s < KITERS; ++s) {
        load_stage(s, s);
        CP_COMMIT();
    }
    for (int it = 0; it < KITERS; ++it) {
        cp_wait<STAGES - 2>();
        __syncthreads();
        if (it + STAGES - 1 < KITERS)
            load_stage((it + STAGES - 1) % STAGES, it + STAGES - 1);
        CP_COMMIT();
        const int buf = it % STAGES;
        k64_compute(sb + (uint32_t)(buf * 2 + 0) * TILE_B,
                    sb + (uint32_t)(buf * 2 + 1) * TILE_B,
                    a_row, a_kc, b_row, b_kc, acc);
    }
}

// GEMM from resident smem tiles: A tiles at aBase+it*TILE_B, B at bBase+it*TILE_B.
template<int KIT>
__device__ __forceinline__ void gemm_smem(uint32_t aBase, uint32_t bBase,
        int wid, int lane, float acc[2][8][4]) {
    LANE_IDX(wid, lane);
    #pragma unroll
    for (int it = 0; it < KIT; ++it)
        k64_compute(aBase + (uint32_t)it * TILE_B, bBase + (uint32_t)it * TILE_B,
                    a_row, a_kc, b_row, b_kc, acc);
}

#define ACC_INIT(acc)                                  \
    _Pragma("unroll")                                  \
    for (int mt = 0; mt < 2; ++mt)                     \
        _Pragma("unroll")                              \
        for (int nt = 0; nt < 8; ++nt)                 \
            _Pragma("unroll")                          \
            for (int q = 0; q < 4; ++q) acc[mt][nt][q] = 0.f;

// ---------------------------------------------------------------------------
// LN1 + NCHW -> window-major (writes xt fp32 and xn fp16)
// ---------------------------------------------------------------------------
__global__ void k_ln1(const float* __restrict__ x,
                      const float* __restrict__ g1,
                      const float* __restrict__ b1,
                      float* __restrict__ xt,
                      __half* __restrict__ xn) {
    __shared__ float sh[128][33];
    __shared__ float red[2][8][32];
    __shared__ float smean[32], srstd[32];

    const int b  = blockIdx.y;
    const int s0 = blockIdx.x * 32;
    const int tp = threadIdx.x & 31;
    const int ty = threadIdx.x >> 5;

    const float* xb = x + (size_t)b * 128 * 16384 + s0;
    float sum = 0.f, sq = 0.f;
    #pragma unroll
    for (int c0 = 0; c0 < 128; c0 += 8) {
        int c = c0 + ty;
        float v = xb[(size_t)c * 16384 + tp];
        sh[c][tp] = v;
        sum += v; sq += v * v;
    }
    red[0][ty][tp] = sum; red[1][ty][tp] = sq;
    __syncthreads();
    if (ty == 0) {
        float s = 0.f, q = 0.f;
        #pragma unroll
        for (int y = 0; y < 8; ++y) { s += red[0][y][tp]; q += red[1][y][tp]; }
        float m = s * (1.0f / 128.0f);
        smean[tp] = m;
        srstd[tp] = rsqrtf(q * (1.0f / 128.0f) - m * m + 1e-5f);
    }
    __syncthreads();

    for (int l = threadIdx.x; l < 32 * 128; l += 256) {
        int p = l >> 7, c = l & 127;
        int s = s0 + p;
        int hh = s >> 7, ww = s & 127;
        int row = ((((b * 32 + (hh >> 2)) * 32 + (ww >> 2)) << 4)
                  + ((hh & 3) << 2) + (ww & 3));
        float v = sh[c][p];
        size_t idx = (size_t)row * 128 + c;
        xt[idx] = v;
        xn[idx] = __float2half_rn((v - smean[p]) * srstd[p] * g1[c] + b1[c]);
    }
}

// ---------------------------------------------------------------------------
// Merged weight prep (one launch): blocks [0,2048) sed, [2048,2176) w_proj,
// [2176,2688) w1, [2688,2816) w2.
// ---------------------------------------------------------------------------
__global__ void k_prep_all(const float* __restrict__ sed_w,
                           const float* __restrict__ w_proj,
                           const float* __restrict__ w1,
                           const float* __restrict__ w2,
                           __half* __restrict__ bt, __half* __restrict__ bp,
                           __half* __restrict__ bw1, __half* __restrict__ bw2) {
    int bx = blockIdx.x;
    if (bx < 2048) {
        int n = bx, nblk = n >> 7, d = n & 127;
        for (int k = threadIdx.x; k < 2048; k += 128) {
            int i = k >> 7, c = k & 127;
            int j = i ^ nblk;
            float s = (float)c_SGN.v[i][j];
            float v = s * __ldg(&sed_w[(size_t)(j * 128 + c) * 128 + d]);
            bt[(size_t)n * 2048 + k] = __float2half_rn(v);
        }
    } else if (bx < 2176) {
        int n = bx - 2048;
        for (int k = threadIdx.x; k < 128; k += 128)
            bp[(size_t)n * 128 + k] = __float2half_rn(__ldg(&w_proj[(size_t)k * 128 + n]));
    } else if (bx < 2688) {
        int n = bx - 2176;
        for (int k = threadIdx.x; k < 128; k += 128)
            bw1[(size_t)n * 128 + k] = __float2half_rn(__ldg(&w1[(size_t)k * 512 + n]));
    } else {
        int n = bx - 2688;
        for (int k = threadIdx.x; k < 512; k += 128)
            bw2[(size_t)n * 512 + k] = __float2half_rn(__ldg(&w2[(size_t)k * 128 + n]));
    }
}

// ---------------------------------------------------------------------------
// FUSED SED + proj + LN2:
//   mainloop: [128 windows x 2048] @ Wbig^T block -> acc (SED), gelu -> smem
//   GEMM2: gA[128x128] @ w_proj -> + b_proj + xt -> y (fp32), LN2 -> yn (fp16)
// CTA (bx, by): pixel slot bx (0..15), windows by*128..+127.
// Global pixel row for local row rl:  p = (by*128 + rl)*16 + bx
// ---------------------------------------------------------------------------
static constexpr int SED_SMEM = 3 * 2 * TILE_B;    // 96 KB (3-stage pipe)

__global__ void __launch_bounds__(256, 2)
k_sedproj(const __half* __restrict__ A, const __half* __restrict__ B,
          const __half* __restrict__ bp,
          const float* __restrict__ bias, const float* __restrict__ xt,
          const float* __restrict__ g2, const float* __restrict__ b2,
          float* __restrict__ y, __half* __restrict__ yn) {
    extern __shared__ __align__(1024) char smem[];
    const uint32_t sb = smem_u32(smem);
    const int tid = threadIdx.x, wid = tid >> 5, lane = tid & 31;
    const int wm = wid & 3, wn = wid >> 2;
    const int mrow0 = blockIdx.y * 128;
    const int n0    = blockIdx.x * 128;   // pixel slot = blockIdx.x

    float acc[2][8][4];
    ACC_INIT(acc);

    gemm128_mainloop<32, 3>(sb, tid, wid, lane,
        (const char*)A + (size_t)mrow0 * 4096,
        (const char*)B + (size_t)n0 * 4096, 4096, acc);
    __syncthreads();   // all warps done with final stage before smem reuse

    // store gelu(acc) as 2 K64 tiles at smem[0..32K)
    #pragma unroll
    for (int mt = 0; mt < 2; ++mt) {
        const int rl0 = wm * 32 + mt * 16 + (lane >> 2);
        #pragma unroll
        for (int nt = 0; nt < 8; ++nt) {
            const int col = wn * 64 + nt * 8 + (lane & 3) * 2;
            float v0 = gelu_exact(acc[mt][nt][0]);
            float v1 = gelu_exact(acc[mt][nt][1]);
            float v2 = gelu_exact(acc[mt][nt][2]);
            float v3 = gelu_exact(acc[mt][nt][3]);
            uint32_t t = (uint32_t)(col >> 6) * TILE_B;
            uint32_t o0 = swz((uint32_t)(rl0 * 128 + (col & 63) * 2));
            uint32_t o1 = swz((uint32_t)((rl0 + 8) * 128 + (col & 63) * 2));
            *(__half2*)(smem + t + o0) =
                __halves2half2(__float2half_rn(v0), __float2half_rn(v1));
            *(__half2*)(smem + t + o1) =
                __halves2half2(__float2half_rn(v2), __float2half_rn(v3));
        }
    }
    // w_proj Bt tiles -> smem[32K..64K)
    load_tile(sb + 2 * TILE_B, (const char*)bp, 256, tid);
    load_tile(sb + 3 * TILE_B, (const char*)bp + 128, 256, tid);
    CP_COMMIT();
    cp_wait<0>();
    __syncthreads();

    // GEMM2: proj
    float acc2[2][8][4];
    ACC_INIT(acc2);
    gemm_smem<2>(sb, sb + 2 * TILE_B, wid, lane, acc2);

    // pass 1: bias + residual, write y, accumulate row sums
    float s_loc[2][2] = {{0.f,0.f},{0.f,0.f}};
    float q_loc[2][2] = {{0.f,0.f},{0.f,0.f}};
    #pragma unroll
    for (int mt = 0; mt < 2; ++mt) {
        const int rl = wm * 32 + mt * 16 + (lane >> 2);
        #pragma unroll
        for (int nt = 0; nt < 8; ++nt) {
            const int col = wn * 64 + nt * 8 + (lane & 3) * 2;
            float bb0 = __ldg(&bias[col]), bb1 = __ldg(&bias[col + 1]);
            const size_t p0 = (size_t)((mrow0 + rl) * 16 + blockIdx.x) * 128 + col;
            const size_t p1 = (size_t)((mrow0 + rl + 8) * 16 + blockIdx.x) * 128 + col;
            float2 a0 = *(const float2*)(xt + p0);
            float2 a1 = *(const float2*)(xt + p1);
            float v0 = acc2[mt][nt][0] + bb0 + a0.x;
            float v1 = acc2[mt][nt][1] + bb1 + a0.y;
            float v2 = acc2[mt][nt][2] + bb0 + a1.x;
            float v3 = acc2[mt][nt][3] + bb1 + a1.y;
            *(float2*)(y + p0) = make_float2(v0, v1);
            *(float2*)(y + p1) = make_float2(v2, v3);
            acc2[mt][nt][0] = v0; acc2[mt][nt][1] = v1;
            acc2[mt][nt][2] = v2; acc2[mt][nt][3] = v3;
            s_loc[mt][0] += v0 + v1; q_loc[mt][0] += v0 * v0 + v1 * v1;
            s_loc[mt][1] += v2 + v3; q_loc[mt][1] += v2 * v2 + v3 * v3;
        }
    }
    #pragma unroll
    for (int mt = 0; mt < 2; ++mt)
        #pragma unroll
        for (int h = 0; h < 2; ++h) {
            float s = s_loc[mt][h], q = q_loc[mt][h];
            s += __shfl_xor_sync(0xffffffffu, s, 1);
            s += __shfl_xor_sync(0xffffffffu, s, 2);
            q += __shfl_xor_sync(0xffffffffu, q, 1);
            q += __shfl_xor_sync(0xffffffffu, q, 2);
            s_loc[mt][h] = s; q_loc[mt][h] = q;
        }
    float* rsum = (float*)(smem + 4 * TILE_B);   // [128][2]
    float* rsq  = rsum + 256;
    __syncthreads();   // gemm_smem readers done before overwrite (safety: region disjoint, keep order)
    if ((lane & 3) == 0) {
        #pragma unroll
        for (int mt = 0; mt < 2; ++mt)
            #pragma unroll
            for (int h = 0; h < 2; ++h) {
                int rl = wm * 32 + mt * 16 + h * 8 + (lane >> 2);
                rsum[rl * 2 + wn] = s_loc[mt][h];
                rsq [rl * 2 + wn] = q_loc[mt][h];
            }
    }
    __syncthreads();

    // pass 2: LN2 normalize -> fp16 yn
    #pragma unroll
    for (int mt = 0; mt < 2; ++mt) {
        const int rl0 = wm * 32 + mt * 16 + (lane >> 2);
        const int rl1 = rl0 + 8;
        float S0 = rsum[rl0 * 2] + rsum[rl0 * 2 + 1];
        float Q0 = rsq [rl0 * 2] + rsq [rl0 * 2 + 1];
        float S1 = rsum[rl1 * 2] + rsum[rl1 * 2 + 1];
        float Q1 = rsq [rl1 * 2] + rsq [rl1 * 2 + 1];
        float mu0 = S0 * (1.0f / 128.0f);
        float rs0 = rsqrtf(Q0 * (1.0f / 128.0f) - mu0 * mu0 + 1e-5f);
        float mu1 = S1 * (1.0f / 128.0f);
        float rs1 = rsqrtf(Q1 * (1.0f / 128.0f) - mu1 * mu1 + 1e-5f);
        #pragma unroll
        for (int nt = 0; nt < 8; ++nt) {
            const int col = wn * 64 + nt * 8 + (lane & 3) * 2;
            float g0 = __ldg(&g2[col]), g1 = __ldg(&g2[col + 1]);
            float be0 = __ldg(&b2[col]), be1 = __ldg(&b2[col + 1]);
            float n0 = (acc2[mt][nt][0] - mu0) * rs0 * g0 + be0;
            float n1 = (acc2[mt][nt][1] - mu0) * rs0 * g1 + be1;
            float n2 = (acc2[mt][nt][2] - mu1) * rs1 * g0 + be0;
            float n3 = (acc2[mt][nt][3] - mu1) * rs1 * g1 + be1;
            const size_t p0 = (size_t)((mrow0 + rl0) * 16 + blockIdx.x) * 128 + col;
            const size_t p1 = (size_t)((mrow0 + rl1) * 16 + blockIdx.x) * 128 + col;
            *(__half2*)(yn + p0) =
                __halves2half2(__float2half_rn(n0), __float2half_rn(n1));
            *(__half2*)(yn + p1) =
                __halves2half2(__float2half_rn(n2), __float2half_rn(n3));
        }
    }
}

// ---------------------------------------------------------------------------
// FUSED MLP: yn[128x128] @ w1 (4 chunks) -> gelu -> @ w2 -> + b2 + y -> NCHW.
// smem: [0,32K) yn A, [32K,64K) h chunk, [64K,96K) w1c, [96K,128K) w2c.
// ---------------------------------------------------------------------------
static constexpr int MLP_SMEM = 8 * TILE_B;   // 128 KB

__global__ void __launch_bounds__(256, 1)
k_mlp(const __half* __restrict__ yn,
      const __half* __restrict__ bw1, const __half* __restrict__ bw2,
      const float* __restrict__ b1v, const float* __restrict__ b2v,
      const float* __restrict__ y, float* __restrict__ out) {
    extern __shared__ __align__(1024) char smem[];
    const uint32_t sb = smem_u32(smem);
    const int tid = threadIdx.x, wid = tid >> 5, lane = tid & 31;
    const int wm = wid & 3, wn = wid >> 2;
    const int mrow0 = blockIdx.x * 128;

    // load yn A tiles (once) + chunk-0 weights
    load_tile(sb + 0 * TILE_B, (const char*)yn + (size_t)mrow0 * 256, 256, tid);
    load_tile(sb + 1 * TILE_B, (const char*)yn + (size_t)mrow0 * 256 + 128, 256, tid);

    float acc2[2][8][4];
    ACC_INIT(acc2);

    for (int c = 0; c < 4; ++c) {
        if (c) __syncthreads();   // prior chunk readers done before overwrite
        // w1 chunk: Bt rows [c*128, c*128+128), K=128 (pitch 256 B)
        load_tile(sb + 4 * TILE_B, (const char*)bw1 + (size_t)c * 128 * 256, 256, tid);
        load_tile(sb + 5 * TILE_B, (const char*)bw1 + (size_t)c * 128 * 256 + 128, 256, tid);
        // w2 chunk: Bt rows 0..127, K slice [c*128, ...) (pitch 1024 B)
        load_tile(sb + 6 * TILE_B, (const char*)bw2 + (size_t)c * 256, 1024, tid);
        load_tile(sb + 7 * TILE_B, (const char*)bw2 + (size_t)c * 256 + 128, 1024, tid);
        CP_COMMIT();
        cp_wait<0>();
        __syncthreads();

        // GEMM1: h_chunk = yn @ w1c
        float acc1[2][8][4];
        ACC_INIT(acc1);
        gemm_smem<2>(sb, sb + 4 * TILE_B, wid, lane, acc1);

        // gelu + b1 -> h tiles at [32K, 64K)
        #pragma unroll
        for (int mt = 0; mt < 2; ++mt) {
            const int rl0 = wm * 32 + mt * 16 + (lane >> 2);
            #pragma unroll
            for (int nt = 0; nt < 8; ++nt) {
                const int col = wn * 64 + nt * 8 + (lane & 3) * 2;
                float bb0 = __ldg(&b1v[c * 128 + col]);
                float bb1 = __ldg(&b1v[c * 128 + col + 1]);
                float v0 = gelu_exact(acc1[mt][nt][0] + bb0);
                float v1 = gelu_exact(acc1[mt][nt][1] + bb1);
                float v2 = gelu_exact(acc1[mt][nt][2] + bb0);
                float v3 = gelu_exact(acc1[mt][nt][3] + bb1);
                uint32_t t = (uint32_t)(2 + (col >> 6)) * TILE_B;
                uint32_t o0 = swz((uint32_t)(rl0 * 128 + (col & 63) * 2));
                uint32_t o1 = swz((uint32_t)((rl0 + 8) * 128 + (col & 63) * 2));
                *(__half2*)(smem + t + o0) =
                    __halves2half2(__float2half_rn(v0), __float2half_rn(v1));
                *(__half2*)(smem + t + o1) =
                    __halves2half2(__float2half_rn(v2), __float2half_rn(v3));
            }
        }
        __syncthreads();

        // GEMM2: out += h_chunk @ w2c
        gemm_smem<2>(sb + 2 * TILE_B, sb + 6 * TILE_B, wid, lane, acc2);
    }
    __syncthreads();   // smem reuse for staging

    // stage final: b2 + y residual into smem [row][col] (pitch 132 floats)
    float* stg = (float*)smem;
    #pragma unroll
    for (int mt = 0; mt < 2; ++mt) {
        const int rl = wm * 32 + mt * 16 + (lane >> 2);
        #pragma unroll
        for (int nt = 0; nt < 8; ++nt) {
            const int col = wn * 64 + nt * 8 + (lane & 3) * 2;
            float bb0 = __ldg(&b2v[col]), bb1 = __ldg(&b2v[col + 1]);
            const size_t o0 = (size_t)(mrow0 + rl) * 128 + col;
            const size_t o1 = (size_t)(mrow0 + rl + 8) * 128 + col;
            float2 a0 = *(const float2*)(y + o0);
            float2 a1 = *(const float2*)(y + o1);
            stg[rl * 132 + col]           = acc2[mt][nt][0] + bb0 + a0.x;
            stg[rl * 132 + col + 1]       = acc2[mt][nt][1] + bb1 + a0.y;
            stg[(rl + 8) * 132 + col]     = acc2[mt][nt][2] + bb0 + a1.x;
            stg[(rl + 8) * 132 + col + 1] = acc2[mt][nt][3] + bb1 + a1.y;
        }
    }
    __syncthreads();

    // coalesced NCHW writeout
    const int widx0 = blockIdx.x * 8;
    const int b   = widx0 >> 10;
    const int h4  = (widx0 >> 5) & 31;
    const int w40 = widx0 & 31;
    for (int seg = wid; seg < 512; seg += 8) {
        int ch = seg >> 2, hh = seg & 3;
        int row = ((lane >> 2) << 4) + (hh << 2) + (lane & 3);
        float val = stg[row * 132 + ch];
        out[(((size_t)(b * 128 + ch)) * 128 + h4 * 4 + hh) * 128
            + w40 * 4 + lane] = val;
    }
}

// ---------------------------------------------------------------------------
// Launch
// ---------------------------------------------------------------------------
extern "C" void kernel_launch(void* const* d_in, const int* in_sizes, int n_in,
                              void* d_out, int out_size) {
    const float* x      = (const float*)d_in[0];
    const float* gamma1 = (const float*)d_in[1];
    const float* beta1  = (const float*)d_in[2];
    const float* sed_w  = (const float*)d_in[3];
    const float* w_proj = (const float*)d_in[4];
    const float* b_proj = (const float*)d_in[5];
    const float* gamma2 = (const float*)d_in[6];
    const float* beta2  = (const float*)d_in[7];
    const float* w1     = (const float*)d_in[8];
    const float* b1     = (const float*)d_in[9];
    const float* w2     = (const float*)d_in[10];
    const float* b2     = (const float*)d_in[11];
    float* out = (float*)d_out;

    float *xt, *y;
    __half *xn, *yn, *bt, *bp, *bw1, *bw2;
    cudaGetSymbolAddress((void**)&xt, g_xt);
    cudaGetSymbolAddress((void**)&y,  g_y);
    cudaGetSymbolAddress((void**)&xn, g_xn);
    cudaGetSymbolAddress((void**)&yn, g_yn);
    cudaGetSymbolAddress((void**)&bt, g_bt);
    cudaGetSymbolAddress((void**)&bp, g_bp);
    cudaGetSymbolAddress((void**)&bw1, g_b1);
    cudaGetSymbolAddress((void**)&bw2, g_b2);

    cudaFuncSetAttribute(k_sedproj, cudaFuncAttributeMaxDynamicSharedMemorySize, SED_SMEM);
    cudaFuncSetAttribute(k_mlp,     cudaFuncAttributeMaxDynamicSharedMemorySize, MLP_SMEM);

    // 0) weight preps (single launch)
    k_prep_all<<<2816, 128>>>(sed_w, w_proj, w1, w2, bt, bp, bw1, bw2);

    // 1) LN1 + transpose
    k_ln1<<<dim3(512, 8), 256>>>(x, gamma1, beta1, xt, xn);

    // 2) SED + gelu + proj + residual + LN2 (fused)
    k_sedproj<<<dim3(16, 64), 256, SED_SMEM>>>(
        xn, bt, bp, b_proj, xt, gamma2, beta2, y, yn);

    // 3) MLP1 + gelu + MLP2 + residual + NCHW (fused)
    k_mlp<<<1024, 256, MLP_SMEM>>>(yn, bw1, bw2, b1, b2, y, out);
}

// round 9
// speedup vs baseline: 2.4984x; 1.0036x over previous
#include <cuda_runtime.h>
#include <cuda_fp16.h>
#include <cstdint>
#include <cstddef>

// ---------------------------------------------------------------------------
// Cayley-Dickson sign table:  e_i * e_j = sign(i,j) * e_{i XOR j}
// ---------------------------------------------------------------------------
constexpr int cdsign(int i, int j, int n) {
    return (n == 1) ? 1
         : (i < n/2 && j < n/2) ? cdsign(i, j, n/2)
         : (i < n/2)            ? cdsign(j - n/2, i, n/2)
         : (j < n/2)            ? cdsign(i - n/2, j, n/2) * (j == 0 ? 1 : -1)
         : -cdsign(j - n/2, i - n/2, n/2) * ((j - n/2) == 0 ? 1 : -1);
}
struct SgnTab { signed char v[16][16]; };
constexpr SgnTab make_sgn() {
    SgnTab t{};
    for (int i = 0; i < 16; ++i)
        for (int j = 0; j < 16; ++j)
            t.v[i][j] = (signed char)cdsign(i, j, 16);
    return t;
}
__constant__ SgnTab c_SGN = make_sgn();

// ---------------------------------------------------------------------------
static constexpr int C = 128, NPIX = 8 * 128 * 128;   // 131072

// fp32 buffers
__device__ float g_xt[NPIX * C];
__device__ float g_y [NPIX * C];

// fp16 operand buffers
__device__ __align__(256) __half g_xn[NPIX * C];
__device__ __align__(256) __half g_yn[NPIX * C];
// weight (B^T, n-major rows of K) buffers
__device__ __align__(256) __half g_bt[2048 * 2048];
__device__ __align__(256) __half g_bp[128 * 128];
__device__ __align__(256) __half g_b1[512 * 128];
__device__ __align__(256) __half g_b2[128 * 512];

// ---------------------------------------------------------------------------
// PTX helpers
// ---------------------------------------------------------------------------
__device__ __forceinline__ uint32_t smem_u32(const void* p) {
    uint32_t a;
    asm("{ .reg .u64 t; cvta.to.shared.u64 t, %1; cvt.u32.u64 %0, t; }"
        : "=r"(a) : "l"(p));
    return a;
}
__device__ __forceinline__ void cp16(uint32_t dst, const void* src) {
    asm volatile("cp.async.cg.shared.global [%0], [%1], 16;" :: "r"(dst), "l"(src));
}
#define CP_COMMIT() asm volatile("cp.async.commit_group;" ::: "memory")
template<int N>
__device__ __forceinline__ void cp_wait() {
    asm volatile("cp.async.wait_group %0;" :: "n"(N) : "memory");
}
__device__ __forceinline__ void ldsm_x4(uint32_t addr, uint32_t* r) {
    asm volatile("ldmatrix.sync.aligned.m8n8.x4.shared.b16 {%0,%1,%2,%3}, [%4];"
        : "=r"(r[0]), "=r"(r[1]), "=r"(r[2]), "=r"(r[3]) : "r"(addr));
}
__device__ __forceinline__ void mma16816(float* c, const uint32_t* a, const uint32_t* b) {
    asm volatile("mma.sync.aligned.m16n8k16.row.col.f32.f16.f16.f32 "
        "{%0,%1,%2,%3}, {%4,%5,%6,%7}, {%8,%9}, {%0,%1,%2,%3};"
        : "+f"(c[0]), "+f"(c[1]), "+f"(c[2]), "+f"(c[3])
        : "r"(a[0]), "r"(a[1]), "r"(a[2]), "r"(a[3]), "r"(b[0]), "r"(b[1]));
}
__device__ __forceinline__ uint32_t swz(uint32_t off) {
    return off ^ ((off >> 3) & 0x70);
}
__device__ __forceinline__ float gelu_exact(float v) {
    return 0.5f * v * (1.0f + erff(v * 0.7071067811865476f));
}

static constexpr int TILE_B = 16384;   // one 128-row x 128-byte (K64) tile

// Load one K64 tile into smem, swizzled. 256 threads.
__device__ __forceinline__ void load_tile(uint32_t dst, const char* src,
                                          size_t pitch, int tid) {
    #pragma unroll
    for (int i = 0; i < 4; ++i) {
        int l = tid + (i << 8);
        int r = l >> 3, ch = l & 7;
        uint32_t off = (uint32_t)(r * 128 + ch * 16);
        cp16(dst + swz(off), src + (size_t)r * pitch + ch * 16);
    }
}
// Same, 512 threads.
__device__ __forceinline__ void load_tile512(uint32_t dst, const char* src,
                                             size_t pitch, int tid) {
    #pragma unroll
    for (int i = 0; i < 2; ++i) {
        int l = tid + (i << 9);
        int r = l >> 3, ch = l & 7;
        uint32_t off = (uint32_t)(r * 128 + ch * 16);
        cp16(dst + swz(off), src + (size_t)r * pitch + ch * 16);
    }
}

// One K64 compute step, 64-wide warp tile (acc[2][8][4]).
__device__ __forceinline__ void k64_compute(uint32_t bA, uint32_t bB,
        int a_row, int a_kc, int b_row, int b_kc, float acc[2][8][4]) {
    #pragma unroll
    for (int ks = 0; ks < 4; ++ks) {
        uint32_t ar[2][4], bb[4][4];
        #pragma unroll
        for (int mt = 0; mt < 2; ++mt) {
            uint32_t off = swz((uint32_t)((a_row + mt * 16) * 128
                                          + (a_kc + 2 * ks) * 16));
            ldsm_x4(bA + off, ar[mt]);
        }
        #pragma unroll
        for (int nt = 0; nt < 4; ++nt) {
            uint32_t off = swz((uint32_t)((b_row + nt * 16) * 128
                                          + (b_kc + 2 * ks) * 16));
            ldsm_x4(bB + off, bb[nt]);
        }
        #pragma unroll
        for (int mt = 0; mt < 2; ++mt)
            #pragma unroll
            for (int nt = 0; nt < 8; ++nt)
                mma16816(acc[mt][nt], ar[mt], &bb[nt >> 1][(nt & 1) * 2]);
    }
}
// One K64 compute step, 32-wide warp tile (acc[2][4][4]).
__device__ __forceinline__ void k64_compute32(uint32_t bA, uint32_t bB,
        int a_row, int a_kc, int b_row, int b_kc, float acc[2][4][4]) {
    #pragma unroll
    for (int ks = 0; ks < 4; ++ks) {
        uint32_t ar[2][4], bb[2][4];
        #pragma unroll
        for (int mt = 0; mt < 2; ++mt) {
            uint32_t off = swz((uint32_t)((a_row + mt * 16) * 128
                                          + (a_kc + 2 * ks) * 16));
            ldsm_x4(bA + off, ar[mt]);
        }
        #pragma unroll
        for (int nt = 0; nt < 2; ++nt) {
            uint32_t off = swz((uint32_t)((b_row + nt * 16) * 128
                                          + (b_kc + 2 * ks) * 16));
            ldsm_x4(bB + off, bb[nt]);
        }
        #pragma unroll
        for (int mt = 0; mt < 2; ++mt)
            #pragma unroll
            for (int nt = 0; nt < 4; ++nt)
                mma16816(acc[mt][nt], ar[mt], &bb[nt >> 1][(nt & 1) * 2]);
    }
}

#define LANE_IDX(wid, lane)                                        \
    const int wm = (wid) & 3, wn = (wid) >> 2;                     \
    const int a_row = wm * 32 + ((lane) & 15);                     \
    const int a_kc  = ((lane) >> 4);                               \
    const int b_row = wn * 64 + ((lane) & 7) + (((lane) >> 4) & 1) * 8; \
    const int b_kc  = (((lane) >> 3) & 1);

// Streamed mainloop: STAGES-deep cp.async pipe over A,B from global (256 thr).
template<int KITERS, int STAGES>
__device__ __forceinline__ void gemm128_mainloop(
        uint32_t sb, int tid, int wid, int lane,
        const char* sA, const char* sB, size_t pitch, float acc[2][8][4]) {
    LANE_IDX(wid, lane);
    auto load_stage = [&](int stage, int kt) {
        load_tile(sb + (uint32_t)(stage * 2 + 0) * TILE_B, sA + (size_t)kt * 128, pitch, tid);
        load_tile(sb + (uint32_t)(stage * 2 + 1) * TILE_B, sB + (size_t)kt * 128, pitch, tid);
    };
    #pragma unroll
    for (int s = 0; s < STAGES - 1 && s < KITERS; ++s) {
        load_stage(s, s);
        CP_COMMIT();
    }
    for (int it = 0; it < KITERS; ++it) {
        cp_wait<STAGES - 2>();
        __syncthreads();
        if (it + STAGES - 1 < KITERS)
            load_stage((it + STAGES - 1) % STAGES, it + STAGES - 1);
        CP_COMMIT();
        const int buf = it % STAGES;
        k64_compute(sb + (uint32_t)(buf * 2 + 0) * TILE_B,
                    sb + (uint32_t)(buf * 2 + 1) * TILE_B,
                    a_row, a_kc, b_row, b_kc, acc);
    }
}

// GEMM from resident smem tiles (64-wide warp tile).
template<int KIT>
__device__ __forceinline__ void gemm_smem(uint32_t aBase, uint32_t bBase,
        int wid, int lane, float acc[2][8][4]) {
    LANE_IDX(wid, lane);
    #pragma unroll
    for (int it = 0; it < KIT; ++it)
        k64_compute(aBase + (uint32_t)it * TILE_B, bBase + (uint32_t)it * TILE_B,
                    a_row, a_kc, b_row, b_kc, acc);
}

#define ACC_INIT(acc)                                  \
    _Pragma("unroll")                                  \
    for (int mt = 0; mt < 2; ++mt)                     \
        _Pragma("unroll")                              \
        for (int nt = 0; nt < 8; ++nt)                 \
            _Pragma("unroll")                          \
            for (int q = 0; q < 4; ++q) acc[mt][nt][q] = 0.f;

#define ACC_INIT32(acc)                                \
    _Pragma("unroll")                                  \
    for (int mt = 0; mt < 2; ++mt)                     \
        _Pragma("unroll")                              \
        for (int nt = 0; nt < 4; ++nt)                 \
            _Pragma("unroll")                          \
            for (int q = 0; q < 4; ++q) acc[mt][nt][q] = 0.f;

// ---------------------------------------------------------------------------
// LN1 + NCHW -> window-major (writes xt fp32 and xn fp16)
// ---------------------------------------------------------------------------
__global__ void k_ln1(const float* __restrict__ x,
                      const float* __restrict__ g1,
                      const float* __restrict__ b1,
                      float* __restrict__ xt,
                      __half* __restrict__ xn) {
    __shared__ float sh[128][33];
    __shared__ float red[2][8][32];
    __shared__ float smean[32], srstd[32];

    const int b  = blockIdx.y;
    const int s0 = blockIdx.x * 32;
    const int tp = threadIdx.x & 31;
    const int ty = threadIdx.x >> 5;

    const float* xb = x + (size_t)b * 128 * 16384 + s0;
    float sum = 0.f, sq = 0.f;
    #pragma unroll
    for (int c0 = 0; c0 < 128; c0 += 8) {
        int c = c0 + ty;
        float v = xb[(size_t)c * 16384 + tp];
        sh[c][tp] = v;
        sum += v; sq += v * v;
    }
    red[0][ty][tp] = sum; red[1][ty][tp] = sq;
    __syncthreads();
    if (ty == 0) {
        float s = 0.f, q = 0.f;
        #pragma unroll
        for (int y = 0; y < 8; ++y) { s += red[0][y][tp]; q += red[1][y][tp]; }
        float m = s * (1.0f / 128.0f);
        smean[tp] = m;
        srstd[tp] = rsqrtf(q * (1.0f / 128.0f) - m * m + 1e-5f);
    }
    __syncthreads();

    for (int l = threadIdx.x; l < 32 * 128; l += 256) {
        int p = l >> 7, c = l & 127;
        int s = s0 + p;
        int hh = s >> 7, ww = s & 127;
        int row = ((((b * 32 + (hh >> 2)) * 32 + (ww >> 2)) << 4)
                  + ((hh & 3) << 2) + (ww & 3));
        float v = sh[c][p];
        size_t idx = (size_t)row * 128 + c;
        xt[idx] = v;
        xn[idx] = __float2half_rn((v - smean[p]) * srstd[p] * g1[c] + b1[c]);
    }
}

// ---------------------------------------------------------------------------
// Merged weight prep (one launch)
// ---------------------------------------------------------------------------
__global__ void k_prep_all(const float* __restrict__ sed_w,
                           const float* __restrict__ w_proj,
                           const float* __restrict__ w1,
                           const float* __restrict__ w2,
                           __half* __restrict__ bt, __half* __restrict__ bp,
                           __half* __restrict__ bw1, __half* __restrict__ bw2) {
    int bx = blockIdx.x;
    if (bx < 2048) {
        int n = bx, nblk = n >> 7, d = n & 127;
        for (int k = threadIdx.x; k < 2048; k += 128) {
            int i = k >> 7, c = k & 127;
            int j = i ^ nblk;
            float s = (float)c_SGN.v[i][j];
            float v = s * __ldg(&sed_w[(size_t)(j * 128 + c) * 128 + d]);
            bt[(size_t)n * 2048 + k] = __float2half_rn(v);
        }
    } else if (bx < 2176) {
        int n = bx - 2048;
        for (int k = threadIdx.x; k < 128; k += 128)
            bp[(size_t)n * 128 + k] = __float2half_rn(__ldg(&w_proj[(size_t)k * 128 + n]));
    } else if (bx < 2688) {
        int n = bx - 2176;
        for (int k = threadIdx.x; k < 128; k += 128)
            bw1[(size_t)n * 128 + k] = __float2half_rn(__ldg(&w1[(size_t)k * 512 + n]));
    } else {
        int n = bx - 2688;
        for (int k = threadIdx.x; k < 512; k += 128)
            bw2[(size_t)n * 512 + k] = __float2half_rn(__ldg(&w2[(size_t)k * 128 + n]));
    }
}

// ---------------------------------------------------------------------------
// FUSED SED + proj + LN2 (unchanged from R8)
// ---------------------------------------------------------------------------
static constexpr int SED_SMEM = 3 * 2 * TILE_B;    // 96 KB

__global__ void __launch_bounds__(256, 2)
k_sedproj(const __half* __restrict__ A, const __half* __restrict__ B,
          const __half* __restrict__ bp,
          const float* __restrict__ bias, const float* __restrict__ xt,
          const float* __restrict__ g2, const float* __restrict__ b2,
          float* __restrict__ y, __half* __restrict__ yn) {
    extern __shared__ __align__(1024) char smem[];
    const uint32_t sb = smem_u32(smem);
    const int tid = threadIdx.x, wid = tid >> 5, lane = tid & 31;
    const int wm = wid & 3, wn = wid >> 2;
    const int mrow0 = blockIdx.y * 128;
    const int n0    = blockIdx.x * 128;

    float acc[2][8][4];
    ACC_INIT(acc);

    gemm128_mainloop<32, 3>(sb, tid, wid, lane,
        (const char*)A + (size_t)mrow0 * 4096,
        (const char*)B + (size_t)n0 * 4096, 4096, acc);
    __syncthreads();

    // store gelu(acc) as 2 K64 tiles at smem[0..32K)
    #pragma unroll
    for (int mt = 0; mt < 2; ++mt) {
        const int rl0 = wm * 32 + mt * 16 + (lane >> 2);
        #pragma unroll
        for (int nt = 0; nt < 8; ++nt) {
            const int col = wn * 64 + nt * 8 + (lane & 3) * 2;
            float v0 = gelu_exact(acc[mt][nt][0]);
            float v1 = gelu_exact(acc[mt][nt][1]);
            float v2 = gelu_exact(acc[mt][nt][2]);
            float v3 = gelu_exact(acc[mt][nt][3]);
            uint32_t t = (uint32_t)(col >> 6) * TILE_B;
            uint32_t o0 = swz((uint32_t)(rl0 * 128 + (col & 63) * 2));
            uint32_t o1 = swz((uint32_t)((rl0 + 8) * 128 + (col & 63) * 2));
            *(__half2*)(smem + t + o0) =
                __halves2half2(__float2half_rn(v0), __float2half_rn(v1));
            *(__half2*)(smem + t + o1) =
                __halves2half2(__float2half_rn(v2), __float2half_rn(v3));
        }
    }
    load_tile(sb + 2 * TILE_B, (const char*)bp, 256, tid);
    load_tile(sb + 3 * TILE_B, (const char*)bp + 128, 256, tid);
    CP_COMMIT();
    cp_wait<0>();
    __syncthreads();

    float acc2[2][8][4];
    ACC_INIT(acc2);
    gemm_smem<2>(sb, sb + 2 * TILE_B, wid, lane, acc2);

    float s_loc[2][2] = {{0.f,0.f},{0.f,0.f}};
    float q_loc[2][2] = {{0.f,0.f},{0.f,0.f}};
    #pragma unroll
    for (int mt = 0; mt < 2; ++mt) {
        const int rl = wm * 32 + mt * 16 + (lane >> 2);
        #pragma unroll
        for (int nt = 0; nt < 8; ++nt) {
            const int col = wn * 64 + nt * 8 + (lane & 3) * 2;
            float bb0 = __ldg(&bias[col]), bb1 = __ldg(&bias[col + 1]);
            const size_t p0 = (size_t)((mrow0 + rl) * 16 + blockIdx.x) * 128 + col;
            const size_t p1 = (size_t)((mrow0 + rl + 8) * 16 + blockIdx.x) * 128 + col;
            float2 a0 = *(const float2*)(xt + p0);
            float2 a1 = *(const float2*)(xt + p1);
            float v0 = acc2[mt][nt][0] + bb0 + a0.x;
            float v1 = acc2[mt][nt][1] + bb1 + a0.y;
            float v2 = acc2[mt][nt][2] + bb0 + a1.x;
            float v3 = acc2[mt][nt][3] + bb1 + a1.y;
            *(float2*)(y + p0) = make_float2(v0, v1);
            *(float2*)(y + p1) = make_float2(v2, v3);
            acc2[mt][nt][0] = v0; acc2[mt][nt][1] = v1;
            acc2[mt][nt][2] = v2; acc2[mt][nt][3] = v3;
            s_loc[mt][0] += v0 + v1; q_loc[mt][0] += v0 * v0 + v1 * v1;
            s_loc[mt][1] += v2 + v3; q_loc[mt][1] += v2 * v2 + v3 * v3;
        }
    }
    #pragma unroll
    for (int mt = 0; mt < 2; ++mt)
        #pragma unroll
        for (int h = 0; h < 2; ++h) {
            float s = s_loc[mt][h], q = q_loc[mt][h];
            s += __shfl_xor_sync(0xffffffffu, s, 1);
            s += __shfl_xor_sync(0xffffffffu, s, 2);
            q += __shfl_xor_sync(0xffffffffu, q, 1);
            q += __shfl_xor_sync(0xffffffffu, q, 2);
            s_loc[mt][h] = s; q_loc[mt][h] = q;
        }
    float* rsum = (float*)(smem + 4 * TILE_B);
    float* rsq  = rsum + 256;
    __syncthreads();
    if ((lane & 3) == 0) {
        #pragma unroll
        for (int mt = 0; mt < 2; ++mt)
            #pragma unroll
            for (int h = 0; h < 2; ++h) {
                int rl = wm * 32 + mt * 16 + h * 8 + (lane >> 2);
                rsum[rl * 2 + wn] = s_loc[mt][h];
                rsq [rl * 2 + wn] = q_loc[mt][h];
            }
    }
    __syncthreads();

    #pragma unroll
    for (int mt = 0; mt < 2; ++mt) {
        const int rl0 = wm * 32 + mt * 16 + (lane >> 2);
        const int rl1 = rl0 + 8;
        float S0 = rsum[rl0 * 2] + rsum[rl0 * 2 + 1];
        float Q0 = rsq [rl0 * 2] + rsq [rl0 * 2 + 1];
        float S1 = rsum[rl1 * 2] + rsum[rl1 * 2 + 1];
        float Q1 = rsq [rl1 * 2] + rsq [rl1 * 2 + 1];
        float mu0 = S0 * (1.0f / 128.0f);
        float rs0 = rsqrtf(Q0 * (1.0f / 128.0f) - mu0 * mu0 + 1e-5f);
        float mu1 = S1 * (1.0f / 128.0f);
        float rs1 = rsqrtf(Q1 * (1.0f / 128.0f) - mu1 * mu1 + 1e-5f);
        #pragma unroll
        for (int nt = 0; nt < 8; ++nt) {
            const int col = wn * 64 + nt * 8 + (lane & 3) * 2;
            float g0 = __ldg(&g2[col]), g1 = __ldg(&g2[col + 1]);
            float be0 = __ldg(&b2[col]), be1 = __ldg(&b2[col + 1]);
            float n0 = (acc2[mt][nt][0] - mu0) * rs0 * g0 + be0;
            float n1 = (acc2[mt][nt][1] - mu0) * rs0 * g1 + be1;
            float n2 = (acc2[mt][nt][2] - mu1) * rs1 * g0 + be0;
            float n3 = (acc2[mt][nt][3] - mu1) * rs1 * g1 + be1;
            const size_t p0 = (size_t)((mrow0 + rl0) * 16 + blockIdx.x) * 128 + col;
            const size_t p1 = (size_t)((mrow0 + rl1) * 16 + blockIdx.x) * 128 + col;
            *(__half2*)(yn + p0) =
                __halves2half2(__float2half_rn(n0), __float2half_rn(n1));
            *(__half2*)(yn + p1) =
                __halves2half2(__float2half_rn(n2), __float2half_rn(n3));
        }
    }
}

// ---------------------------------------------------------------------------
// FUSED MLP, 512 threads / 16 warps, 32x32 warp tiles, double-buffered weights.
// smem tiles: 0-1 yn A, 2-3 h, 4-7 weights buf0 (w1c:4-5, w2c:6-7),
//             8-11 weights buf1.  Total 12 tiles = 192 KB.
// ---------------------------------------------------------------------------
static constexpr int MLP_SMEM = 12 * TILE_B;   // 192 KB

__global__ void __launch_bounds__(512, 1)
k_mlp(const __half* __restrict__ yn,
      const __half* __restrict__ bw1, const __half* __restrict__ bw2,
      const float* __restrict__ b1v, const float* __restrict__ b2v,
      const float* __restrict__ y, float* __restrict__ out) {
    extern __shared__ __align__(1024) char smem[];
    const uint32_t sb = smem_u32(smem);
    const int tid = threadIdx.x, wid = tid >> 5, lane = tid & 31;
    const int wm = wid & 3, wn = wid >> 2;        // 4m x 4n warps
    const int mrow0 = blockIdx.x * 128;

    const int a_row = wm * 32 + (lane & 15);
    const int a_kc  = lane >> 4;
    const int b_row = wn * 32 + (lane & 7) + ((lane >> 4) & 1) * 8;
    const int b_kc  = (lane >> 3) & 1;

    // yn A tiles (resident all chunks) + chunk-0 weights into buf0
    load_tile512(sb + 0 * TILE_B, (const char*)yn + (size_t)mrow0 * 256, 256, tid);
    load_tile512(sb + 1 * TILE_B, (const char*)yn + (size_t)mrow0 * 256 + 128, 256, tid);
    load_tile512(sb + 4 * TILE_B, (const char*)bw1, 256, tid);
    load_tile512(sb + 5 * TILE_B, (const char*)bw1 + 128, 256, tid);
    load_tile512(sb + 6 * TILE_B, (const char*)bw2, 1024, tid);
    load_tile512(sb + 7 * TILE_B, (const char*)bw2 + 128, 1024, tid);
    CP_COMMIT();

    float acc2[2][4][4];
    ACC_INIT32(acc2);

    #pragma unroll
    for (int c = 0; c < 4; ++c) {
        if (c) __syncthreads();   // prior-iter readers done before buffer overwrite
        if (c + 1 < 4) {
            uint32_t wb = sb + (uint32_t)(4 + 4 * ((c + 1) & 1)) * TILE_B;
            load_tile512(wb + 0 * TILE_B, (const char*)bw1 + (size_t)(c + 1) * 128 * 256, 256, tid);
            load_tile512(wb + 1 * TILE_B, (const char*)bw1 + (size_t)(c + 1) * 128 * 256 + 128, 256, tid);
            load_tile512(wb + 2 * TILE_B, (const char*)bw2 + (size_t)(c + 1) * 256, 1024, tid);
            load_tile512(wb + 3 * TILE_B, (const char*)bw2 + (size_t)(c + 1) * 256 + 128, 1024, tid);
        }
        CP_COMMIT();
        if (c + 1 < 4) cp_wait<1>(); else cp_wait<0>();
        __syncthreads();

        const uint32_t wb = sb + (uint32_t)(4 + 4 * (c & 1)) * TILE_B;

        // GEMM1: h_chunk = yn @ w1c
        float acc1[2][4][4];
        ACC_INIT32(acc1);
        #pragma unroll
        for (int it = 0; it < 2; ++it)
            k64_compute32(sb + (uint32_t)it * TILE_B, wb + (uint32_t)it * TILE_B,
                          a_row, a_kc, b_row, b_kc, acc1);

        // gelu + b1 -> h tiles 2-3
        #pragma unroll
        for (int mt = 0; mt < 2; ++mt) {
            const int rl0 = wm * 32 + mt * 16 + (lane >> 2);
            #pragma unroll
            for (int nt = 0; nt < 4; ++nt) {
                const int col = wn * 32 + nt * 8 + (lane & 3) * 2;
                float bb0 = __ldg(&b1v[c * 128 + col]);
                float bb1 = __ldg(&b1v[c * 128 + col + 1]);
                float v0 = gelu_exact(acc1[mt][nt][0] + bb0);
                float v1 = gelu_exact(acc1[mt][nt][1] + bb1);
                float v2 = gelu_exact(acc1[mt][nt][2] + bb0);
                float v3 = gelu_exact(acc1[mt][nt][3] + bb1);
                uint32_t t = (uint32_t)(2 + (col >> 6)) * TILE_B;
                uint32_t o0 = swz((uint32_t)(rl0 * 128 + (col & 63) * 2));
                uint32_t o1 = swz((uint32_t)((rl0 + 8) * 128 + (col & 63) * 2));
                *(__half2*)(smem + t + o0) =
                    __halves2half2(__float2half_rn(v0), __float2half_rn(v1));
                *(__half2*)(smem + t + o1) =
                    __halves2half2(__float2half_rn(v2), __float2half_rn(v3));
            }
        }
        __syncthreads();

        // GEMM2: out += h_chunk @ w2c
        #pragma unroll
        for (int it = 0; it < 2; ++it)
            k64_compute32(sb + (uint32_t)(2 + it) * TILE_B,
                          wb + (uint32_t)(2 + it) * TILE_B,
                          a_row, a_kc, b_row, b_kc, acc2);
    }
    __syncthreads();   // smem reuse for staging

    // stage final: b2 + y residual into smem [row][col] (pitch 132 floats)
    float* stg = (float*)smem;
    #pragma unroll
    for (int mt = 0; mt < 2; ++mt) {
        const int rl = wm * 32 + mt * 16 + (lane >> 2);
        #pragma unroll
        for (int nt = 0; nt < 4; ++nt) {
            const int col = wn * 32 + nt * 8 + (lane & 3) * 2;
            float bb0 = __ldg(&b2v[col]), bb1 = __ldg(&b2v[col + 1]);
            const size_t o0 = (size_t)(mrow0 + rl) * 128 + col;
            const size_t o1 = (size_t)(mrow0 + rl + 8) * 128 + col;
            float2 a0 = *(const float2*)(y + o0);
            float2 a1 = *(const float2*)(y + o1);
            stg[rl * 132 + col]           = acc2[mt][nt][0] + bb0 + a0.x;
            stg[rl * 132 + col + 1]       = acc2[mt][nt][1] + bb1 + a0.y;
            stg[(rl + 8) * 132 + col]     = acc2[mt][nt][2] + bb0 + a1.x;
            stg[(rl + 8) * 132 + col + 1] = acc2[mt][nt][3] + bb1 + a1.y;
        }
    }
    __syncthreads();

    // coalesced NCHW writeout
    const int widx0 = blockIdx.x * 8;
    const int b   = widx0 >> 10;
    const int h4  = (widx0 >> 5) & 31;
    const int w40 = widx0 & 31;
    for (int seg = wid; seg < 512; seg += 16) {
        int ch = seg >> 2, hh = seg & 3;
        int row = ((lane >> 2) << 4) + (hh << 2) + (lane & 3);
        float val = stg[row * 132 + ch];
        out[(((size_t)(b * 128 + ch)) * 128 + h4 * 4 + hh) * 128
            + w40 * 4 + lane] = val;
    }
}

// ---------------------------------------------------------------------------
// Launch
// ---------------------------------------------------------------------------
extern "C" void kernel_launch(void* const* d_in, const int* in_sizes, int n_in,
                              void* d_out, int out_size) {
    const float* x      = (const float*)d_in[0];
    const float* gamma1 = (const float*)d_in[1];
    const float* beta1  = (const float*)d_in[2];
    const float* sed_w  = (const float*)d_in[3];
    const float* w_proj = (const float*)d_in[4];
    const float* b_proj = (const float*)d_in[5];
    const float* gamma2 = (const float*)d_in[6];
    const float* beta2  = (const float*)d_in[7];
    const float* w1     = (const float*)d_in[8];
    const float* b1     = (const float*)d_in[9];
    const float* w2     = (const float*)d_in[10];
    const float* b2     = (const float*)d_in[11];
    float* out = (float*)d_out;

    float *xt, *y;
    __half *xn, *yn, *bt, *bp, *bw1, *bw2;
    cudaGetSymbolAddress((void**)&xt, g_xt);
    cudaGetSymbolAddress((void**)&y,  g_y);
    cudaGetSymbolAddress((void**)&xn, g_xn);
    cudaGetSymbolAddress((void**)&yn, g_yn);
    cudaGetSymbolAddress((void**)&bt, g_bt);
    cudaGetSymbolAddress((void**)&bp, g_bp);
    cudaGetSymbolAddress((void**)&bw1, g_b1);
    cudaGetSymbolAddress((void**)&bw2, g_b2);

    cudaFuncSetAttribute(k_sedproj, cudaFuncAttributeMaxDynamicSharedMemorySize, SED_SMEM);
    cudaFuncSetAttribute(k_mlp,     cudaFuncAttributeMaxDynamicSharedMemorySize, MLP_SMEM);

    // 0) weight preps (single launch)
    k_prep_all<<<2816, 128>>>(sed_w, w_proj, w1, w2, bt, bp, bw1, bw2);

    // 1) LN1 + transpose
    k_ln1<<<dim3(512, 8), 256>>>(x, gamma1, beta1, xt, xn);

    // 2) SED + gelu + proj + residual + LN2 (fused)
    k_sedproj<<<dim3(16, 64), 256, SED_SMEM>>>(
        xn, bt, bp, b_proj, xt, gamma2, beta2, y, yn);

    // 3) MLP1 + gelu + MLP2 + residual + NCHW (fused, 512 threads)
    k_mlp<<<1024, 512, MLP_SMEM>>>(yn, bw1, bw2, b1, b2, y, out);
}